// round 16
// baseline (speedup 1.0000x reference)
#include <cuda_runtime.h>
#include <cuda_bf16.h>
#include <math.h>
#include <stdint.h>

#define MROWS 93312          // B*N*D = 128*81*9
#define BN_TOT 10368         // B*N

typedef unsigned long long u64;

// ---------------- device scratch (static, no allocation) ----------------
__device__ __align__(16) float d_h   [MROWS*96];
__device__ __align__(16) float d_c   [MROWS*96];
__device__ __align__(16) float d_t1  [MROWS*96];
__device__ __align__(16) float d_t2  [MROWS*96];
__device__ __align__(16) float d_t3  [MROWS*96];
__device__ __align__(16) float d_t4  [MROWS*96];   // fallback chain scratch
__device__ __align__(16) float d_t5  [MROWS*96];   // fallback chain scratch (parallel branch)
__device__ __align__(16) float d_md  [MROWS*96];
__device__ __align__(16) float d_S   [BN_TOT*96];  // per-(b,n) digit-sum of t1
__device__ __align__(16) float d_gates[MROWS*384]; // fallback LSTM scratch
__device__ __align__(16) float d_xcat[3*96];
__device__ __align__(16) float d_xw1 [3*96];
__device__ __align__(16) float d_biasC[384];
// bf16 split weights: 12 square mats (transposed to [n][k]) + LSTM ih/hh ([384,96] = [n][k])
__device__ __align__(16) __nv_bfloat16 d_Wsq_hi[12*9216];
__device__ __align__(16) __nv_bfloat16 d_Wsq_lo[12*9216];
__device__ __align__(16) __nv_bfloat16 d_Wih_hi[36864];
__device__ __align__(16) __nv_bfloat16 d_Wih_lo[36864];
__device__ __align__(16) __nv_bfloat16 d_Whh_hi[36864];
__device__ __align__(16) __nv_bfloat16 d_Whh_lo[36864];
__device__ int   d_nbr[81*20];
__device__ unsigned char d_cat[MROWS];

// ---------------- helpers ----------------
__device__ __forceinline__ float sigf(float x)  { return 1.f / (1.f + __expf(-x)); }
__device__ __forceinline__ float tanhff(float x){ return 1.f - 2.f / (__expf(2.f * x) + 1.f); }

struct alignas(8) bpair { __nv_bfloat162 a, b; };

__device__ __forceinline__ void bsplit4(float4 v, bpair& hi, bpair& lo) {
    __nv_bfloat162 h01 = __floats2bfloat162_rn(v.x, v.y);
    __nv_bfloat162 h23 = __floats2bfloat162_rn(v.z, v.w);
    float2 f01 = __bfloat1622float2(h01);
    float2 f23 = __bfloat1622float2(h23);
    hi.a = h01; hi.b = h23;
    lo.a = __floats2bfloat162_rn(v.x - f01.x, v.y - f01.y);
    lo.b = __floats2bfloat162_rn(v.z - f23.x, v.w - f23.y);
}

__device__ __forceinline__ uint32_t smem_u32(const void* p) {
    uint32_t a;
    asm("{ .reg .u64 t; cvta.to.shared.u64 t, %1; cvt.u32.u64 %0, t; }" : "=r"(a) : "l"(p));
    return a;
}
__device__ __forceinline__ uint32_t elect1() {
    uint32_t r;
    asm volatile("{ .reg .pred p; elect.sync _|p, 0xFFFFFFFF; selp.b32 %0, 1, 0, p; }" : "=r"(r));
    return r;
}
__device__ __forceinline__ void mbar_init(uint32_t a, uint32_t cnt) {
    asm volatile("mbarrier.init.shared.b64 [%0], %1;" :: "r"(a), "r"(cnt) : "memory");
}
__device__ __forceinline__ void mbar_inval(uint32_t a) {
    asm volatile("mbarrier.inval.shared.b64 [%0];" :: "r"(a) : "memory");
}
__device__ __forceinline__ void mbar_wait(uint32_t a, uint32_t parity) {
    asm volatile(
        "{\n\t.reg .pred P;\n\t"
        "W_%=:\n\t"
        "mbarrier.try_wait.parity.acquire.cta.shared::cta.b64 P, [%0], %1, 0x989680;\n\t"
        "@P bra D_%=;\n\t"
        "bra W_%=;\n\t"
        "D_%=:\n\t}"
        :: "r"(a), "r"(parity) : "memory");
}
__device__ __forceinline__ void mma_bf16(uint32_t d, uint64_t ad, uint64_t bd,
                                         uint32_t idesc, uint32_t en) {
    asm volatile(
        "{\n\t.reg .pred p;\n\tsetp.ne.u32 p, %5, 0;\n\t"
        "tcgen05.mma.cta_group::1.kind::f16 [%0], %1, %2, %3, {%4, %4, %4, %4}, p;\n\t}"
        :: "r"(d), "l"(ad), "l"(bd), "r"(idesc), "r"(0u), "r"(en) : "memory");
}
__device__ __forceinline__ void tc_commit(uint32_t mbar) {
    asm volatile(
        "tcgen05.commit.cta_group::1.mbarrier::arrive::one.shared::cluster.b64 [%0];"
        :: "r"(mbar) : "memory");
}
#define TC_ALLOC(sa, n)   asm volatile("tcgen05.alloc.cta_group::1.sync.aligned.shared::cta.b32 [%0], %1;" :: "r"(sa), "r"(n) : "memory")
#define TC_RELINQ()       asm volatile("tcgen05.relinquish_alloc_permit.cta_group::1.sync.aligned;")
#define TC_DEALLOC(t, n)  asm volatile("tcgen05.dealloc.cta_group::1.sync.aligned.b32 %0, %1;" :: "r"(t), "r"(n))
#define TC_WAIT_LD()      asm volatile("tcgen05.wait::ld.sync.aligned;" ::: "memory")
#define TC_WAIT_ST()      asm volatile("tcgen05.wait::st.sync.aligned;" ::: "memory")
#define TC_FENCE_BEFORE() asm volatile("tcgen05.fence::before_thread_sync;" ::: "memory")
#define TC_FENCE_AFTER()  asm volatile("tcgen05.fence::after_thread_sync;" ::: "memory")
#define FENCE_ASYNC()     asm volatile("fence.proxy.async.shared::cta;" ::: "memory")

#define LDTM_X32(r, a) \
    asm volatile("tcgen05.ld.sync.aligned.32x32b.x32.b32 " \
        "{%0,%1,%2,%3,%4,%5,%6,%7,%8,%9,%10,%11,%12,%13,%14,%15," \
        "%16,%17,%18,%19,%20,%21,%22,%23,%24,%25,%26,%27,%28,%29,%30,%31}, [%32];" \
        : "=r"((r)[0]),"=r"((r)[1]),"=r"((r)[2]),"=r"((r)[3]),"=r"((r)[4]),"=r"((r)[5]),"=r"((r)[6]),"=r"((r)[7]), \
          "=r"((r)[8]),"=r"((r)[9]),"=r"((r)[10]),"=r"((r)[11]),"=r"((r)[12]),"=r"((r)[13]),"=r"((r)[14]),"=r"((r)[15]), \
          "=r"((r)[16]),"=r"((r)[17]),"=r"((r)[18]),"=r"((r)[19]),"=r"((r)[20]),"=r"((r)[21]),"=r"((r)[22]),"=r"((r)[23]), \
          "=r"((r)[24]),"=r"((r)[25]),"=r"((r)[26]),"=r"((r)[27]),"=r"((r)[28]),"=r"((r)[29]),"=r"((r)[30]),"=r"((r)[31]) \
        : "r"(a))
#define LDTM_X16(r, a) \
    asm volatile("tcgen05.ld.sync.aligned.32x32b.x16.b32 " \
        "{%0,%1,%2,%3,%4,%5,%6,%7,%8,%9,%10,%11,%12,%13,%14,%15}, [%16];" \
        : "=r"((r)[0]),"=r"((r)[1]),"=r"((r)[2]),"=r"((r)[3]),"=r"((r)[4]),"=r"((r)[5]),"=r"((r)[6]),"=r"((r)[7]), \
          "=r"((r)[8]),"=r"((r)[9]),"=r"((r)[10]),"=r"((r)[11]),"=r"((r)[12]),"=r"((r)[13]),"=r"((r)[14]),"=r"((r)[15]) \
        : "r"(a))
#define STTM_X16(a, r) \
    asm volatile("tcgen05.st.sync.aligned.32x32b.x16.b32 [%0], " \
        "{%1,%2,%3,%4,%5,%6,%7,%8,%9,%10,%11,%12,%13,%14,%15,%16};" \
        :: "r"(a), \
           "r"((r)[0]),"r"((r)[1]),"r"((r)[2]),"r"((r)[3]),"r"((r)[4]),"r"((r)[5]),"r"((r)[6]),"r"((r)[7]), \
           "r"((r)[8]),"r"((r)[9]),"r"((r)[10]),"r"((r)[11]),"r"((r)[12]),"r"((r)[13]),"r"((r)[14]),"r"((r)[15]) \
        : "memory")

// ---------------- prep ----------------
__global__ void prep_kernel(const float* __restrict__ encW1, const float* __restrict__ encb1,
                            const float* __restrict__ encW2, const float* __restrict__ encb2,
                            const float* __restrict__ gmW1,  const float* __restrict__ gmb1,
                            const float* __restrict__ bih,   const float* __restrict__ bhh)
{
    int tid = threadIdx.x;
    if (tid < 288) {
        int k = tid / 96, j = tid % 96;
        float acc = encb2[j];
        #pragma unroll
        for (int i = 0; i < 16; i++) {
            float e = fmaxf(encW1[k*16 + i] + encb1[i], 0.f);
            acc += e * encW2[i*96 + j];
        }
        d_xcat[tid] = acc;
    }
    if (tid < 384) d_biasC[tid] = bih[tid] + bhh[tid];
    __syncthreads();
    if (tid < 288) {
        int k = tid / 96, j = tid % 96;
        float acc = gmb1[j];
        for (int t = 0; t < 96; t++) acc += d_xcat[k*96 + t] * gmW1[t*96 + j];
        d_xw1[tid] = acc;
    }
    if (tid < 81) {
        int m = tid, cnt = 0;
        int r = m / 9, c = m % 9, br = r / 3, bc = c / 3;
        for (int n = 0; n < 81; n++) {
            if (n == m) continue;
            int r2 = n / 9, c2 = n % 9;
            if (r2 == r || c2 == c || (r2/3 == br && c2/3 == bc)) d_nbr[m*20 + cnt++] = n;
        }
    }
}

// ---------------- weight split/transposes (once per run) ----------------
struct Ptr12 { const float* p[12]; };
__global__ void split_sq_kernel(Ptr12 srcs)
{
    int m = blockIdx.y;
    int idx = blockIdx.x * 256 + threadIdx.x;
    if (idx >= 9216) return;
    int k = idx / 96, n = idx % 96;
    float v = srcs.p[m][k*96 + n];
    __nv_bfloat16 hi = __float2bfloat16(v);
    d_Wsq_hi[m*9216 + n*96 + k] = hi;
    d_Wsq_lo[m*9216 + n*96 + k] = __float2bfloat16(v - __bfloat162float(hi));
}
__global__ void split_lstm_kernel(const float* __restrict__ Wih, const float* __restrict__ Whh)
{
    int idx = blockIdx.x * 256 + threadIdx.x;
    if (idx >= 36864) return;
    float v = Wih[idx];
    __nv_bfloat16 hi = __float2bfloat16(v);
    d_Wih_hi[idx] = hi; d_Wih_lo[idx] = __float2bfloat16(v - __bfloat162float(hi));
    v = Whh[idx];
    hi = __float2bfloat16(v);
    d_Whh_hi[idx] = hi; d_Whh_lo[idx] = __float2bfloat16(v - __bfloat162float(hi));
}

// ---------------- init ----------------
__global__ void init_kernel(const int* __restrict__ inputs, const float* __restrict__ c0)
{
    int idx = blockIdx.x * blockDim.x + threadIdx.x;  // MROWS*24
    if (idx >= MROWS * 24) return;
    int r = idx / 24, q = idx % 24;
    int bn = r / 9, dd = r % 9;
    int v = inputs[bn];
    int cat = (v == 0) ? 0 : ((v == dd + 1) ? 1 : 2);
    if (q == 0) d_cat[r] = (unsigned char)cat;
    *(float4*)(d_h + (size_t)r*96 + q*4) = *(const float4*)(d_xcat + cat*96 + q*4);
    *(float4*)(d_c + (size_t)r*96 + q*4) = *(const float4*)(c0 + (size_t)r*96 + q*4);
}

// ---------------- SMEM layout (bf16 SW64 blocked atoms) ----------------
#define SA_HI 1024
#define SA_LO 25600
#define SW_HI 50176
#define SW_LO 68608
#define SMEM_BYTES 87040

__device__ __forceinline__ uint32_t swA(int r, int k) {
    uint32_t byte = (uint32_t)((r >> 3) + (k >> 5) * 16) * 512u
                  + (uint32_t)(r & 7) * 64u + (uint32_t)(k & 31) * 2u;
    return byte ^ ((byte >> 3) & 0x30);
}
__device__ __forceinline__ uint32_t swW(int n, int k) {
    uint32_t byte = (uint32_t)((n >> 3) + (k >> 5) * 12) * 512u
                  + (uint32_t)(n & 7) * 64u + (uint32_t)(k & 31) * 2u;
    return byte ^ ((byte >> 3) & 0x30);
}

#define IDESC_BF16 ((1u<<4) | (1u<<7) | (1u<<10) | (12u<<17) | (8u<<24))
#define DBASE_SW64 ((4ull<<61) | (1ull<<46) | (32ull<<32) | (1ull<<16))

__device__ __forceinline__ void mma_layer(uint32_t dtm, uint64_t ah, uint64_t al,
                                          uint64_t wh, uint64_t wl, bool accum) {
    #pragma unroll
    for (int j = 0; j < 6; j++) {
        uint64_t aoff = (uint64_t)((j >> 1) * 512 + (j & 1) * 2);
        uint64_t woff = (uint64_t)((j >> 1) * 384 + (j & 1) * 2);
        mma_bf16(dtm, ah + aoff, wh + woff, IDESC_BF16, (!accum && j == 0) ? 0u : 1u);
        mma_bf16(dtm, al + aoff, wh + woff, IDESC_BF16, 1u);
        mma_bf16(dtm, ah + aoff, wl + woff, IDESC_BF16, 1u);
    }
}

template<int NSRC>
__device__ __forceinline__ int lw_off(int l, int src) {
    return (l == 0 ? src : (NSRC - 1 + l)) * 9216;
}

__device__ __forceinline__ void load_split_A(char* smem, const float* A, int row0, int tid) {
    #pragma unroll
    for (int i = 0; i < 12; i++) {
        int idx = i * 256 + tid;
        int rA = idx / 24, k = (idx % 24) * 4;
        float4 v = *(const float4*)(A + (size_t)(row0 + rA)*96 + k);
        bpair hi, lo;
        bsplit4(v, hi, lo);
        uint32_t sw = swA(rA, k);
        *(bpair*)(smem + SA_HI + sw) = hi;
        *(bpair*)(smem + SA_LO + sw) = lo;
    }
}
// A = S[bn] - t1[r]  (msg_cell computed on the fly)
__device__ __forceinline__ void load_split_A_mc(char* smem, const float* t1,
                                                const float* S, int row0, int tid) {
    #pragma unroll
    for (int i = 0; i < 12; i++) {
        int idx = i * 256 + tid;
        int rA = idx / 24, k = (idx % 24) * 4;
        int r = row0 + rA;
        float4 a = *(const float4*)(t1 + (size_t)r*96 + k);
        float4 s = *(const float4*)(S + (size_t)(r/9)*96 + k);
        float4 v = make_float4(s.x - a.x, s.y - a.y, s.z - a.z, s.w - a.w);
        bpair hi, lo;
        bsplit4(v, hi, lo);
        uint32_t sw = swA(rA, k);
        *(bpair*)(smem + SA_HI + sw) = hi;
        *(bpair*)(smem + SA_LO + sw) = lo;
    }
}
__device__ __forceinline__ void load_W(char* smem, const __nv_bfloat16* Wh,
                                       const __nv_bfloat16* Wl, int tid) {
    #pragma unroll
    for (int i = 0; i < 9; i++) {
        int idx = i * 256 + tid;
        int n = idx / 24, k = (idx % 24) * 4;
        uint32_t sw = swW(n, k);
        *(uint2*)(smem + SW_HI + sw) = *(const uint2*)(Wh + (size_t)n*96 + k);
        *(uint2*)(smem + SW_LO + sw) = *(const uint2*)(Wl + (size_t)n*96 + k);
    }
}

// ---- W prefetch: LDG into regs (overlaps mbar wait), STS after wait ----
#define LDG_W(Wh_, Wl_) do {                                                  \
    const __nv_bfloat16* _wh = (Wh_);                                         \
    const __nv_bfloat16* _wl = (Wl_);                                         \
    _Pragma("unroll")                                                         \
    for (int i = 0; i < 9; i++) {                                             \
        int idx = i * 256 + tid;                                              \
        int n = idx / 24, k = (idx % 24) * 4;                                 \
        wph[i] = *(const uint2*)(_wh + (size_t)n*96 + k);                     \
        wpl[i] = *(const uint2*)(_wl + (size_t)n*96 + k);                     \
    }                                                                         \
} while (0)
#define STS_W() do {                                                          \
    _Pragma("unroll")                                                         \
    for (int i = 0; i < 9; i++) {                                             \
        int idx = i * 256 + tid;                                              \
        int n = idx / 24, k = (idx % 24) * 4;                                 \
        uint32_t sw = swW(n, k);                                              \
        *(uint2*)(smem + SW_HI + sw) = wph[i];                                \
        *(uint2*)(smem + SW_LO + sw) = wpl[i];                                \
    }                                                                         \
} while (0)

// =====================================================================
// Fused MLP chain (bf16x3): NL layers, intermediates on-chip.
// BIAS0: 1 = layer0 bias is xw1[cat]. EPIF: 0 = plain store; 3 = head.
// FBSCR: fallback scratch selector. MCMODE: 1 = src0 A is S[bn]-A0[r].
// =====================================================================
template<int NL, int NSRC, int BIAS0, int EPIF, int FBSCR, int MCMODE>
__global__ void __launch_bounds__(256, 2) tchain_kernel(
    const float* __restrict__ A0, const float* __restrict__ A1,
    const __nv_bfloat16* __restrict__ Whi, const __nv_bfloat16* __restrict__ Wlo,
    const float* __restrict__ biases, const float* __restrict__ w3,
    const float* __restrict__ b3, float* __restrict__ C,
    const float* __restrict__ Sp)
{
#if defined(__CUDA_ARCH_FEAT_SM103_ALL)
    extern __shared__ char smem[];
    const uint32_t sb = smem_u32(smem);
    const int tid = threadIdx.x;
    const int warp = tid >> 5;
    const int lane = tid & 31;
    const int row0 = blockIdx.x * 128;

    if (warp == 0) { TC_ALLOC(sb, 256); TC_RELINQ(); }
    if (tid == 0)  mbar_init(sb + 8, 1);
    __syncthreads();
    uint32_t tmem;
    asm volatile("ld.shared.b32 %0, [%1];" : "=r"(tmem) : "r"(sb));

    const uint64_t ahd = DBASE_SW64 | (((uint64_t)(sb + SA_HI) >> 4) & 0x3FFF);
    const uint64_t ald = DBASE_SW64 | (((uint64_t)(sb + SA_LO) >> 4) & 0x3FFF);
    const uint64_t whd = DBASE_SW64 | (((uint64_t)(sb + SW_HI) >> 4) & 0x3FFF);
    const uint64_t wld = DBASE_SW64 | (((uint64_t)(sb + SW_LO) >> 4) & 0x3FFF);
    int wave = 0;
    uint2 wph[9], wpl[9];

    const int sub  = warp & 3;
    const int half = warp >> 2;
    const int rr   = sub * 32 + lane;
    const int r    = row0 + rr;
    const uint32_t woff = (uint32_t)sub << 21;
    const int coff = half * 48;

    LDG_W(Whi + lw_off<NSRC>(0, 0), Wlo + lw_off<NSRC>(0, 0));

    #pragma unroll
    for (int src = 0; src < NSRC; src++) {
        if (MCMODE == 1 && src == 0)
            load_split_A_mc(smem, A0, Sp, row0, tid);
        else
            load_split_A(smem, src ? A1 : A0, row0, tid);
        STS_W();
        FENCE_ASYNC();
        __syncthreads();
        if (warp == 0 && elect1()) {
            mma_layer(tmem, ahd, ald, whd, wld, src != 0);
            tc_commit(sb + 8);
        }
        if (src + 1 < NSRC)
            LDG_W(Whi + lw_off<NSRC>(0, src + 1), Wlo + lw_off<NSRC>(0, src + 1));
        else if (NL > 1)
            LDG_W(Whi + lw_off<NSRC>(1, 0), Wlo + lw_off<NSRC>(1, 0));
        mbar_wait(sb + 8, wave & 1); wave++;
    }

    #pragma unroll
    for (int l = 1; l < NL; l++) {
        STS_W();
        TC_FENCE_AFTER();
        uint32_t dsel = (uint32_t)((l - 1) & 1) * 128u;
        uint32_t dreg[48];
        LDTM_X32(dreg,      tmem + dsel + woff + coff);
        LDTM_X16(dreg + 32, tmem + dsel + woff + coff + 32);
        TC_WAIT_LD();
        float vals[48];
        {
            const int lprev = l - 1;
            const float* bv = (BIAS0 == 1 && lprev == 0)
                            ? (d_xw1 + (int)d_cat[r]*96 + coff)
                            : (biases + (lprev - BIAS0)*96 + coff);
            #pragma unroll
            for (int u = 0; u < 48; u++)
                vals[u] = fmaxf(__uint_as_float(dreg[u]) + bv[u], 0.f);
        }
        #pragma unroll
        for (int u4 = 0; u4 < 12; u4++) {
            int k = coff + u4*4;
            float4 v = make_float4(vals[u4*4], vals[u4*4+1], vals[u4*4+2], vals[u4*4+3]);
            bpair hi, lo;
            bsplit4(v, hi, lo);
            uint32_t sw = swA(rr, k);
            *(bpair*)(smem + SA_HI + sw) = hi;
            *(bpair*)(smem + SA_LO + sw) = lo;
        }
        FENCE_ASYNC();
        __syncthreads();
        if (warp == 0 && elect1()) {
            mma_layer(tmem + (uint32_t)(l & 1) * 128u, ahd, ald, whd, wld, false);
            tc_commit(sb + 8);
        }
        if (l + 1 < NL)
            LDG_W(Whi + lw_off<NSRC>(l + 1, 0), Wlo + lw_off<NSRC>(l + 1, 0));
        mbar_wait(sb + 8, wave & 1); wave++;
    }

    TC_FENCE_AFTER();
    {
        uint32_t dsel = (uint32_t)((NL - 1) & 1) * 128u;
        uint32_t dreg[48];
        LDTM_X32(dreg,      tmem + dsel + woff + coff);
        LDTM_X16(dreg + 32, tmem + dsel + woff + coff + 32);
        TC_WAIT_LD();
        const int lf = NL - 1;
        const float* bv = (BIAS0 == 1 && lf == 0)
                        ? (d_xw1 + (int)d_cat[r]*96 + coff)
                        : (biases + (lf - BIAS0)*96 + coff);
        if (EPIF == 3) {
            float part = 0.f;
            #pragma unroll
            for (int u = 0; u < 48; u++) {
                float v = fmaxf(__uint_as_float(dreg[u]) + bv[u], 0.f);
                part += v * w3[coff + u];
            }
            float* red = (float*)(smem + SA_HI);
            __syncthreads();
            red[tid] = part;
            __syncthreads();
            if (warp < 4)
                C[r] = red[tid] + red[tid + 128] + b3[0];
        } else {
            float vals[48];
            #pragma unroll
            for (int u = 0; u < 48; u++)
                vals[u] = __uint_as_float(dreg[u]) + bv[u];
            #pragma unroll
            for (int u = 0; u < 12; u++)
                *(float4*)(C + (size_t)r*96 + coff + u*4) = *(float4*)(vals + u*4);
        }
    }

    __syncthreads();
    if (tid == 0) mbar_inval(sb + 8);
    if (warp == 0) { TC_DEALLOC(tmem, 256); }
#else
    // ================= fallback (plain sm_103): FFMA layer loop =====
    float* scratch = FBSCR ? d_t5 : d_t4;
    __shared__ float As[16][132];
    __shared__ float Bs[16][97];
    const int tid = threadIdx.x;
    const int tx  = tid & 15;
    const int ty  = tid >> 4;
    const int row0 = blockIdx.x * 128;
    const int qk = tid & 3;
    const int rrf = tid >> 2;

    #pragma unroll 1
    for (int l = 0; l < NL; l++) {
        float acc[8][6];
        #pragma unroll
        for (int i = 0; i < 8; i++)
            #pragma unroll
            for (int u = 0; u < 6; u++) acc[i][u] = 0.f;
        const int ns = (l == 0) ? NSRC : 1;
        #pragma unroll 1
        for (int s = 0; s < ns; s++) {
            const float* A = (l == 0) ? (s ? A1 : A0) : scratch;
            const bool mc = (MCMODE == 1 && l == 0 && s == 0);
            const __nv_bfloat16* Wh = Whi + lw_off<NSRC>(l, s);
            const __nv_bfloat16* Wl = Wlo + lw_off<NSRC>(l, s);
            #pragma unroll 1
            for (int ct = 0; ct < 6; ct++) {
                const int k0 = ct * 16;
                float4 v0 = *(const float4*)(A + (size_t)(row0 + rrf     )*96 + k0 + qk*4);
                float4 v1 = *(const float4*)(A + (size_t)(row0 + rrf + 64)*96 + k0 + qk*4);
                if (mc) {
                    float4 s0 = *(const float4*)(Sp + (size_t)((row0 + rrf     )/9)*96 + k0 + qk*4);
                    float4 s1 = *(const float4*)(Sp + (size_t)((row0 + rrf + 64)/9)*96 + k0 + qk*4);
                    v0 = make_float4(s0.x - v0.x, s0.y - v0.y, s0.z - v0.z, s0.w - v0.w);
                    v1 = make_float4(s1.x - v1.x, s1.y - v1.y, s1.z - v1.z, s1.w - v1.w);
                }
                float bl[6];
                #pragma unroll
                for (int u = 0; u < 6; u++) {
                    int idx = tid + 256*u;
                    int n = idx >> 4, kk = idx & 15;
                    bl[u] = __bfloat162float(Wh[(size_t)n*96 + k0 + kk])
                          + __bfloat162float(Wl[(size_t)n*96 + k0 + kk]);
                }
                __syncthreads();
                As[qk*4+0][rrf]    = v0.x; As[qk*4+1][rrf]    = v0.y;
                As[qk*4+2][rrf]    = v0.z; As[qk*4+3][rrf]    = v0.w;
                As[qk*4+0][rrf+64] = v1.x; As[qk*4+1][rrf+64] = v1.y;
                As[qk*4+2][rrf+64] = v1.z; As[qk*4+3][rrf+64] = v1.w;
                #pragma unroll
                for (int u = 0; u < 6; u++) {
                    int idx = tid + 256*u;
                    Bs[idx & 15][idx >> 4] = bl[u];
                }
                __syncthreads();
                #pragma unroll
                for (int k = 0; k < 16; k++) {
                    float a[8];
                    #pragma unroll
                    for (int i = 0; i < 8; i++) a[i] = As[k][ty*8 + i];
                    float b[6];
                    #pragma unroll
                    for (int u = 0; u < 6; u++) b[u] = Bs[k][tx + 16*u];
                    #pragma unroll
                    for (int i = 0; i < 8; i++)
                        #pragma unroll
                        for (int u = 0; u < 6; u++) acc[i][u] = fmaf(a[i], b[u], acc[i][u]);
                }
            }
        }
        const bool relu = (l < NL - 1) || (EPIF == 3);
        const bool last = (l == NL - 1);
        float* dst = (last && EPIF == 0) ? C : scratch;
        float bv[6];
        if (!(BIAS0 == 1 && l == 0)) {
            #pragma unroll
            for (int u = 0; u < 6; u++) bv[u] = biases[(l - BIAS0)*96 + tx + 16*u];
        }
        #pragma unroll
        for (int i = 0; i < 8; i++) {
            int rW = row0 + ty*8 + i;
            const float* xb = (BIAS0 == 1 && l == 0) ? (d_xw1 + (int)d_cat[rW]*96) : nullptr;
            #pragma unroll
            for (int u = 0; u < 6; u++) {
                float v = acc[i][u] + ((BIAS0 == 1 && l == 0) ? xb[tx + 16*u] : bv[u]);
                if (relu) v = fmaxf(v, 0.f);
                dst[(size_t)rW*96 + tx + 16*u] = v;
            }
        }
        __syncthreads();
    }
    if (EPIF == 3) {
        const int warp = tid >> 5, lane = tid & 31;
        for (int i = 0; i < 16; i++) {
            int r = row0 + warp*16 + i;
            const float* x = scratch + (size_t)r*96;
            float s = x[lane]*w3[lane] + x[lane+32]*w3[lane+32] + x[lane+64]*w3[lane+64];
            #pragma unroll
            for (int o = 16; o; o >>= 1) s += __shfl_xor_sync(0xffffffffu, s, o);
            if (lane == 0) C[r] = s + b3[0];
        }
    }
#endif
}

// =====================================================================
// LSTM GEMM: TMEM 256 (2 banks of 96), gates in phases (i,g)->(f)->(o),
// u / tanh(c') staged through TMEM bank X1 via STTM. occ 2, W prefetch.
// =====================================================================
__global__ void __launch_bounds__(256, 2) tlstm_kernel(
    const float* __restrict__ A0, const float* __restrict__ A1,
    const __nv_bfloat16* __restrict__ W0hi, const __nv_bfloat16* __restrict__ W0lo,
    const __nv_bfloat16* __restrict__ W1hi, const __nv_bfloat16* __restrict__ W1lo,
    const float* __restrict__ bias, float* __restrict__ C, float* __restrict__ cst)
{
#if defined(__CUDA_ARCH_FEAT_SM103_ALL)
    extern __shared__ char smem[];
    const uint32_t sb = smem_u32(smem);
    const int tid = threadIdx.x;
    const int warp = tid >> 5;
    const int lane = tid & 31;
    const int row0 = blockIdx.x * 128;

    if (warp == 0) { TC_ALLOC(sb, 256); TC_RELINQ(); }
    if (tid == 0)  mbar_init(sb + 8, 1);
    __syncthreads();
    uint32_t tmem;
    asm volatile("ld.shared.b32 %0, [%1];" : "=r"(tmem) : "r"(sb));

    const uint64_t ahd = DBASE_SW64 | (((uint64_t)(sb + SA_HI) >> 4) & 0x3FFF);
    const uint64_t ald = DBASE_SW64 | (((uint64_t)(sb + SA_LO) >> 4) & 0x3FFF);
    const uint64_t whd = DBASE_SW64 | (((uint64_t)(sb + SW_HI) >> 4) & 0x3FFF);
    const uint64_t wld = DBASE_SW64 | (((uint64_t)(sb + SW_LO) >> 4) & 0x3FFF);
    int wave = 0;
    uint2 wph[9], wpl[9];

    const int sub  = warp & 3;
    const int half = warp >> 2;
    const int r    = row0 + sub * 32 + lane;
    const uint32_t woff = (uint32_t)sub << 21;
    const int coff = half * 48;

// stage: STS prefetched W, (opt) load A, sync, MMA+commit, prefetch next W, wait
#define LSTM_STAGE(bank_, acc_, APTR_, NWh_, NWl_) do {                       \
    STS_W();                                                                  \
    if ((const float*)(APTR_) != nullptr)                                     \
        load_split_A(smem, (const float*)(APTR_), row0, tid);                 \
    FENCE_ASYNC();                                                            \
    __syncthreads();                                                          \
    if (warp == 0 && elect1()) {                                              \
        mma_layer(tmem + (bank_), ahd, ald, whd, wld, (acc_));                \
        tc_commit(sb + 8);                                                    \
    }                                                                         \
    if ((const __nv_bfloat16*)(NWh_) != nullptr)                              \
        LDG_W((const __nv_bfloat16*)(NWh_), (const __nv_bfloat16*)(NWl_));    \
    mbar_wait(sb + 8, wave & 1); wave++;                                      \
} while (0)

    LDG_W(W0hi, W0lo);                                    // Wih_i
    // ---- phase 1: gates i (bank0), g (bank96) ----
    LSTM_STAGE(0,  false, A0,      W0hi + 2*9216, W0lo + 2*9216);  // t3 @ Wih_i ; next Wih_g
    LSTM_STAGE(96, false, nullptr, W1hi,          W1lo);           // t3 @ Wih_g ; next Whh_i
    LSTM_STAGE(0,  true,  A1,      W1hi + 2*9216, W1lo + 2*9216);  // h  @ Whh_i ; next Whh_g
    LSTM_STAGE(96, true,  nullptr, W1hi + 1*9216, W1lo + 1*9216);  // h  @ Whh_g ; next Whh_f

    // E1: u = sig(i+bi) * tanh(g+bg)  -> STTM into bank0
    TC_FENCE_AFTER();
    #pragma unroll
    for (int ch = 0; ch < 3; ch++) {
        int col = coff + ch * 16;
        uint32_t ireg[16], greg[16], ureg[16];
        LDTM_X16(ireg, tmem + woff + col);
        LDTM_X16(greg, tmem + 96 + woff + col);
        TC_WAIT_LD();
        #pragma unroll
        for (int u = 0; u < 16; u++) {
            float iv = sigf(__uint_as_float(ireg[u]) + bias[col + u]);
            float gv = tanhff(__uint_as_float(greg[u]) + bias[192 + col + u]);
            ureg[u] = __float_as_uint(iv * gv);
        }
        STTM_X16(tmem + woff + col, ureg);
    }
    TC_WAIT_ST();
    TC_FENCE_BEFORE();
    __syncthreads();

    // ---- phase 2a: gate f (bank96) ----
    LSTM_STAGE(96, false, nullptr, W0hi + 1*9216, W0lo + 1*9216);  // h  @ Whh_f ; next Wih_f
    LSTM_STAGE(96, true,  A0,      W0hi + 3*9216, W0lo + 3*9216);  // t3 @ Wih_f ; next Wih_o

    // E2: c' = sig(f+bf)*c_old + u; store c'; STTM tanh(c') -> bank0
    TC_FENCE_AFTER();
    #pragma unroll
    for (int ch = 0; ch < 3; ch++) {
        int col = coff + ch * 16;
        uint32_t freg[16], ureg[16], treg[16];
        LDTM_X16(freg, tmem + 96 + woff + col);
        LDTM_X16(ureg, tmem + woff + col);
        TC_WAIT_LD();
        float ncv[16];
        #pragma unroll
        for (int u4 = 0; u4 < 4; u4++) {
            float4 cold = *(const float4*)(cst + (size_t)r*96 + col + u4*4);
            float co[4] = {cold.x, cold.y, cold.z, cold.w};
            #pragma unroll
            for (int e = 0; e < 4; e++) {
                int u = u4*4 + e;
                float fv = sigf(__uint_as_float(freg[u]) + bias[96 + col + u]);
                float nc = fv * co[e] + __uint_as_float(ureg[u]);
                ncv[u] = nc;
                treg[u] = __float_as_uint(tanhff(nc));
            }
        }
        #pragma unroll
        for (int u4 = 0; u4 < 4; u4++)
            *(float4*)(cst + (size_t)r*96 + col + u4*4) = *(float4*)(ncv + u4*4);
        STTM_X16(tmem + woff + col, treg);
    }
    TC_WAIT_ST();
    TC_FENCE_BEFORE();
    __syncthreads();

    // ---- phase 2b: gate o (bank96) ----
    LSTM_STAGE(96, false, nullptr, W1hi + 3*9216, W1lo + 3*9216);  // t3 @ Wih_o ; next Whh_o
    LSTM_STAGE(96, true,  A1,      nullptr,       nullptr);        // h  @ Whh_o

    // E3: h' = sig(o+bo) * tanh(c')
    TC_FENCE_AFTER();
    #pragma unroll
    for (int ch = 0; ch < 3; ch++) {
        int col = coff + ch * 16;
        uint32_t oreg[16], treg[16];
        LDTM_X16(oreg, tmem + 96 + woff + col);
        LDTM_X16(treg, tmem + woff + col);
        TC_WAIT_LD();
        float hv[16];
        #pragma unroll
        for (int u = 0; u < 16; u++) {
            float ov = sigf(__uint_as_float(oreg[u]) + bias[288 + col + u]);
            hv[u] = ov * __uint_as_float(treg[u]);
        }
        #pragma unroll
        for (int u4 = 0; u4 < 4; u4++)
            *(float4*)(C + (size_t)r*96 + col + u4*4) = *(float4*)(hv + u4*4);
    }

    __syncthreads();
    if (tid == 0) mbar_inval(sb + 8);
    if (warp == 0) { TC_DEALLOC(tmem, 256); }
#undef LSTM_STAGE
#else
    // fallback: gates to d_gates then fused elementwise
    __shared__ float As[16][132];
    __shared__ float Bs[16][97];
    const int tid = threadIdx.x;
    const int tx  = tid & 15;
    const int ty  = tid >> 4;
    const int row0 = blockIdx.x * 128;
    const int qk = tid & 3;
    const int rrf = tid >> 2;

    #pragma unroll 1
    for (int g = 0; g < 4; g++) {
        float acc[8][6];
        #pragma unroll
        for (int i = 0; i < 8; i++)
            #pragma unroll
            for (int u = 0; u < 6; u++) acc[i][u] = 0.f;
        #pragma unroll
        for (int s = 0; s < 2; s++) {
            const float* A = s ? A1 : A0;
            const __nv_bfloat16* Wh = (s ? W1hi : W0hi) + (size_t)g*9216;
            const __nv_bfloat16* Wl = (s ? W1lo : W0lo) + (size_t)g*9216;
            #pragma unroll 1
            for (int ct = 0; ct < 6; ct++) {
                const int k0 = ct * 16;
                float4 v0 = *(const float4*)(A + (size_t)(row0 + rrf     )*96 + k0 + qk*4);
                float4 v1 = *(const float4*)(A + (size_t)(row0 + rrf + 64)*96 + k0 + qk*4);
                float bl[6];
                #pragma unroll
                for (int u = 0; u < 6; u++) {
                    int idx = tid + 256*u;
                    int n = idx >> 4, kk = idx & 15;
                    bl[u] = __bfloat162float(Wh[(size_t)n*96 + k0 + kk])
                          + __bfloat162float(Wl[(size_t)n*96 + k0 + kk]);
                }
                __syncthreads();
                As[qk*4+0][rrf]    = v0.x; As[qk*4+1][rrf]    = v0.y;
                As[qk*4+2][rrf]    = v0.z; As[qk*4+3][rrf]    = v0.w;
                As[qk*4+0][rrf+64] = v1.x; As[qk*4+1][rrf+64] = v1.y;
                As[qk*4+2][rrf+64] = v1.z; As[qk*4+3][rrf+64] = v1.w;
                #pragma unroll
                for (int u = 0; u < 6; u++) {
                    int idx = tid + 256*u;
                    Bs[idx & 15][idx >> 4] = bl[u];
                }
                __syncthreads();
                #pragma unroll
                for (int k = 0; k < 16; k++) {
                    float a[8];
                    #pragma unroll
                    for (int i = 0; i < 8; i++) a[i] = As[k][ty*8 + i];
                    float b[6];
                    #pragma unroll
                    for (int u = 0; u < 6; u++) b[u] = Bs[k][tx + 16*u];
                    #pragma unroll
                    for (int i = 0; i < 8; i++)
                        #pragma unroll
                        for (int u = 0; u < 6; u++) acc[i][u] = fmaf(a[i], b[u], acc[i][u]);
                }
            }
        }
        #pragma unroll
        for (int i = 0; i < 8; i++) {
            int rW = row0 + ty*8 + i;
            #pragma unroll
            for (int u = 0; u < 6; u++)
                d_gates[(size_t)rW*384 + g*96 + tx + 16*u] = acc[i][u] + bias[g*96 + tx + 16*u];
        }
    }
    __syncthreads();
    #pragma unroll
    for (int u = 0; u < 12; u++) {
        int e = tid + u*256;
        int r = row0 + e/24, q = (e%24)*4;
        const float* gp = d_gates + (size_t)r*384 + q;
        float4 gi = *(const float4*)(gp);
        float4 gf = *(const float4*)(gp + 96);
        float4 gg = *(const float4*)(gp + 192);
        float4 go = *(const float4*)(gp + 288);
        float4 co = *(const float4*)(cst + (size_t)r*96 + q);
        float4 nc, nh;
        nc.x = sigf(gf.x)*co.x + sigf(gi.x)*tanhff(gg.x);  nh.x = sigf(go.x)*tanhff(nc.x);
        nc.y = sigf(gf.y)*co.y + sigf(gi.y)*tanhff(gg.y);  nh.y = sigf(go.y)*tanhff(nc.y);
        nc.z = sigf(gf.z)*co.z + sigf(gi.z)*tanhff(gg.z);  nh.z = sigf(go.z)*tanhff(nc.z);
        nc.w = sigf(gf.w)*co.w + sigf(gi.w)*tanhff(gg.w);  nh.w = sigf(go.w)*tanhff(nc.w);
        *(float4*)(cst + (size_t)r*96 + q) = nc;
        *(float4*)(C   + (size_t)r*96 + q) = nh;
    }
#endif
}

// ---------------- msgS: S[bn] = sum_d t1[bn*9+d] ----------------
__global__ void msgS_kernel(const float* __restrict__ in, float* __restrict__ S)
{
    int idx = blockIdx.x * blockDim.x + threadIdx.x;
    if (idx >= BN_TOT * 24) return;
    int bn = idx / 24, q = idx % 24;
    const float* base = in + (size_t)bn*9*96 + q*4;
    float sx = 0, sy = 0, sz = 0, sw = 0;
    #pragma unroll
    for (int d = 0; d < 9; d++) {
        float4 x = *(const float4*)(base + d*96);
        sx += x.x; sy += x.y; sz += x.z; sw += x.w;
    }
    float4 o; o.x = sx; o.y = sy; o.z = sz; o.w = sw;
    *(float4*)(S + (size_t)bn*96 + q*4) = o;
}

// ---------------- msg_digit ----------------
__global__ void msgdigit_kernel(const float* __restrict__ in, float* __restrict__ out)
{
    __shared__ float4 sIn[81*24];
    __shared__ int snbr[81*20];
    int b = blockIdx.x, cz = blockIdx.y;
    const float* gbase = in + (size_t)b*81*864 + cz*96;
    for (int idx = threadIdx.x; idx < 81*24; idx += 256) {
        int n = idx / 24, q = idx % 24;
        sIn[n*24 + q] = *(const float4*)(gbase + (size_t)n*864 + q*4);
    }
    for (int idx = threadIdx.x; idx < 81*20; idx += 256) snbr[idx] = d_nbr[idx];
    __syncthreads();
    float* obase = out + (size_t)b*81*864 + cz*96;
    for (int idx = threadIdx.x; idx < 81*24; idx += 256) {
        int m = idx / 24, q = idx % 24;
        const int* nb = snbr + m*20;
        float4 s = {0.f, 0.f, 0.f, 0.f};
        #pragma unroll
        for (int e = 0; e < 20; e++) {
            float4 v = sIn[nb[e]*24 + q];
            s.x += v.x; s.y += v.y; s.z += v.z; s.w += v.w;
        }
        *(float4*)(obase + (size_t)m*864 + q*4) = s;
    }
}

// ---------------- static stream/event context ----------------
struct StreamCtx {
    cudaStream_t s1, s2;
    cudaEvent_t fork[5], j1[5], j2[5];
    bool ok;
    StreamCtx() : ok(false) {
        if (cudaStreamCreateWithFlags(&s1, cudaStreamNonBlocking) != cudaSuccess) return;
        if (cudaStreamCreateWithFlags(&s2, cudaStreamNonBlocking) != cudaSuccess) return;
        for (int i = 0; i < 5; i++) {
            if (cudaEventCreateWithFlags(&fork[i], cudaEventDisableTiming) != cudaSuccess) return;
            if (cudaEventCreateWithFlags(&j1[i],   cudaEventDisableTiming) != cudaSuccess) return;
            if (cudaEventCreateWithFlags(&j2[i],   cudaEventDisableTiming) != cudaSuccess) return;
        }
        ok = true;
    }
};
static StreamCtx g_ctx;

// ---------------- launch ----------------
extern "C" void kernel_launch(void* const* d_in, const int* in_sizes, int n_in,
                              void* d_out, int out_size)
{
    const int*   inputs = (const int*)  d_in[0];
    const float* c0     = (const float*)d_in[1];
    const float* encW1  = (const float*)d_in[4];
    const float* encb1  = (const float*)d_in[5];
    const float* encW2  = (const float*)d_in[6];
    const float* encb2  = (const float*)d_in[7];
    const float* crW    = (const float*)d_in[8];
    const float* crb    = (const float*)d_in[9];
    const float* drW    = (const float*)d_in[10];
    const float* drb    = (const float*)d_in[11];
    const float* gmW1   = (const float*)d_in[12];
    const float* gmb1   = (const float*)d_in[13];
    const float* gmW2   = (const float*)d_in[14];
    const float* gmb2   = (const float*)d_in[15];
    const float* Wih    = (const float*)d_in[16];
    const float* Whh    = (const float*)d_in[17];
    const float* bih    = (const float*)d_in[18];
    const float* bhh    = (const float*)d_in[19];
    const float* rW12   = (const float*)d_in[20];
    const float* rb12   = (const float*)d_in[21];
    const float* rW3    = (const float*)d_in[22];
    const float* rb3    = (const float*)d_in[23];
    float* out = (float*)d_out;

    float *h, *c, *t1, *t2, *t3, *md, *S, *biasC;
    __nv_bfloat16 *sqhi, *sqlo, *ihhi, *ihlo, *hhhi, *hhlo;
    cudaGetSymbolAddress((void**)&h,     d_h);
    cudaGetSymbolAddress((void**)&c,     d_c);
    cudaGetSymbolAddress((void**)&t1,    d_t1);
    cudaGetSymbolAddress((void**)&t2,    d_t2);
    cudaGetSymbolAddress((void**)&t3,    d_t3);
    cudaGetSymbolAddress((void**)&md,    d_md);
    cudaGetSymbolAddress((void**)&S,     d_S);
    cudaGetSymbolAddress((void**)&biasC, d_biasC);
    cudaGetSymbolAddress((void**)&sqhi,  d_Wsq_hi);
    cudaGetSymbolAddress((void**)&sqlo,  d_Wsq_lo);
    cudaGetSymbolAddress((void**)&ihhi,  d_Wih_hi);
    cudaGetSymbolAddress((void**)&ihlo,  d_Wih_lo);
    cudaGetSymbolAddress((void**)&hhhi,  d_Whh_hi);
    cudaGetSymbolAddress((void**)&hhlo,  d_Whh_lo);

    cudaFuncAttributes fa;
    cudaFuncGetAttributes(&fa, tchain_kernel<3,1,0,0,0,0>);
    const bool tc = (fa.sharedSizeBytes < 4096);
    const size_t SH = tc ? (size_t)SMEM_BYTES : 0;
    if (tc) {
        cudaFuncSetAttribute(tchain_kernel<3,1,0,0,0,0>, cudaFuncAttributeMaxDynamicSharedMemorySize, SMEM_BYTES);
        cudaFuncSetAttribute(tchain_kernel<3,1,0,0,1,0>, cudaFuncAttributeMaxDynamicSharedMemorySize, SMEM_BYTES);
        cudaFuncSetAttribute(tchain_kernel<3,2,1,0,0,1>, cudaFuncAttributeMaxDynamicSharedMemorySize, SMEM_BYTES);
        cudaFuncSetAttribute(tchain_kernel<2,1,0,3,0,0>, cudaFuncAttributeMaxDynamicSharedMemorySize, SMEM_BYTES);
        cudaFuncSetAttribute(tlstm_kernel, cudaFuncAttributeMaxDynamicSharedMemorySize, SMEM_BYTES);
    }

    const bool par = g_ctx.ok;
    cudaStream_t s0 = 0;
    cudaStream_t s1 = par ? g_ctx.s1 : s0;
    cudaStream_t s2 = par ? g_ctx.s2 : s0;

    prep_kernel<<<1, 384, 0, s0>>>(encW1, encb1, encW2, encb2, gmW1, gmb1, bih, bhh);
    Ptr12 ps;
    ps.p[0] = crW;          ps.p[1] = crW + 9216;   ps.p[2] = crW + 18432;
    ps.p[3] = drW;          ps.p[4] = drW + 9216;   ps.p[5] = drW + 18432;
    ps.p[6] = gmW1 + 9216;  ps.p[7] = gmW1 + 18432;
    ps.p[8] = gmW2;         ps.p[9] = gmW2 + 9216;
    ps.p[10] = rW12;        ps.p[11] = rW12 + 9216;
    split_sq_kernel<<<dim3(36, 12), 256, 0, s0>>>(ps);
    split_lstm_kernel<<<144, 256, 0, s0>>>(Wih, Whh);
    init_kernel<<<8748, 256, 0, s0>>>(inputs, c0);

    #define HI(i) (sqhi + (i)*9216)
    #define LO(i) (sqlo + (i)*9216)

    // --- pre-loop: t1/S, md from initial h (cr ∥ dr) ---
    if (par) {
        cudaEventRecord(g_ctx.fork[4], s0);
        cudaStreamWaitEvent(s1, g_ctx.fork[4], 0);
        cudaStreamWaitEvent(s2, g_ctx.fork[4], 0);
    }
    tchain_kernel<3,1,0,0,0,0><<<729,256,SH,s1>>>(h, nullptr, HI(0), LO(0), crb, nullptr, nullptr, t1, nullptr);
    msgS_kernel<<<972, 256, 0, s1>>>(t1, S);
    tchain_kernel<3,1,0,0,1,0><<<729,256,SH,s2>>>(h, nullptr, HI(3), LO(3), drb, nullptr, nullptr, t2, nullptr);
    msgdigit_kernel<<<dim3(128, 9), 256, 0, s2>>>(t2, md);
    if (par) {
        cudaEventRecord(g_ctx.j1[4], s1);
        cudaEventRecord(g_ctx.j2[4], s2);
        cudaStreamWaitEvent(s0, g_ctx.j1[4], 0);
        cudaStreamWaitEvent(s0, g_ctx.j2[4], 0);
    }

    for (int it = 0; it < 4; it++) {
        // serial spine: g-MLP (mc computed on the fly from t1/S) then LSTM
        tchain_kernel<3,2,1,0,0,1><<<729,256,SH,s0>>>(t1, md, HI(6), LO(6), gmb2, nullptr, nullptr, t3, S);
        tlstm_kernel<<<729,256,SH,s0>>>(t3, h, ihhi, ihlo, hhhi, hhlo, biasC, h, c);
        // parallel consumers of new h: head ∥ (cr→msgS) ∥ (dr→msgdigit)
        if (it < 3) {
            if (par) {
                cudaEventRecord(g_ctx.fork[it], s0);
                cudaStreamWaitEvent(s1, g_ctx.fork[it], 0);
                cudaStreamWaitEvent(s2, g_ctx.fork[it], 0);
            }
            tchain_kernel<3,1,0,0,0,0><<<729,256,SH,s1>>>(h, nullptr, HI(0), LO(0), crb, nullptr, nullptr, t1, nullptr);
            msgS_kernel<<<972, 256, 0, s1>>>(t1, S);
            tchain_kernel<3,1,0,0,1,0><<<729,256,SH,s2>>>(h, nullptr, HI(3), LO(3), drb, nullptr, nullptr, t2, nullptr);
            msgdigit_kernel<<<dim3(128, 9), 256, 0, s2>>>(t2, md);
            tchain_kernel<2,1,0,3,0,0><<<729,256,SH,s0>>>(h, nullptr, HI(10), LO(10), rb12, rW3, rb3, out + (size_t)it * MROWS, nullptr);
            if (par) {
                cudaEventRecord(g_ctx.j1[it], s1);
                cudaEventRecord(g_ctx.j2[it], s2);
                cudaStreamWaitEvent(s0, g_ctx.j1[it], 0);
                cudaStreamWaitEvent(s0, g_ctx.j2[it], 0);
            }
        } else {
            tchain_kernel<2,1,0,3,0,0><<<729,256,SH,s0>>>(h, nullptr, HI(10), LO(10), rb12, rW3, rb3, out + (size_t)it * MROWS, nullptr);
        }
    }
    #undef HI
    #undef LO
}

// round 17
// speedup vs baseline: 1.0142x; 1.0142x over previous
#include <cuda_runtime.h>
#include <cuda_bf16.h>
#include <math.h>
#include <stdint.h>

#define MROWS 93312          // B*N*D = 128*81*9
#define BN_TOT 10368         // B*N

typedef unsigned long long u64;

// ---------------- device scratch (static, no allocation) ----------------
__device__ __align__(16) float d_h   [MROWS*96];
__device__ __align__(16) float d_c   [MROWS*96];
__device__ __align__(16) float d_t1  [MROWS*96];
__device__ __align__(16) float d_t2  [MROWS*96];
__device__ __align__(16) float d_t3  [MROWS*96];
__device__ __align__(16) float d_t4  [MROWS*96];   // fallback chain scratch
__device__ __align__(16) float d_t5  [MROWS*96];   // fallback chain scratch (parallel branch)
__device__ __align__(16) float d_md  [MROWS*96];
__device__ __align__(16) float d_S   [BN_TOT*96];  // per-(b,n) digit-sum of t1
__device__ __align__(16) float d_gates[MROWS*384]; // fallback LSTM scratch
__device__ __align__(16) float d_xcat[3*96];
__device__ __align__(16) float d_xw1 [3*96];
__device__ __align__(16) float d_biasC[384];
// bf16 split weights: 12 square mats (transposed to [n][k]) + LSTM ih/hh ([384,96] = [n][k])
__device__ __align__(16) __nv_bfloat16 d_Wsq_hi[12*9216];
__device__ __align__(16) __nv_bfloat16 d_Wsq_lo[12*9216];
__device__ __align__(16) __nv_bfloat16 d_Wih_hi[36864];
__device__ __align__(16) __nv_bfloat16 d_Wih_lo[36864];
__device__ __align__(16) __nv_bfloat16 d_Whh_hi[36864];
__device__ __align__(16) __nv_bfloat16 d_Whh_lo[36864];
__device__ int   d_nbr[81*20];
__device__ unsigned char d_cat[MROWS];

// ---------------- helpers ----------------
__device__ __forceinline__ float sigf(float x)  { return 1.f / (1.f + __expf(-x)); }
__device__ __forceinline__ float tanhff(float x){ return 1.f - 2.f / (__expf(2.f * x) + 1.f); }

struct alignas(8) bpair { __nv_bfloat162 a, b; };

__device__ __forceinline__ void bsplit4(float4 v, bpair& hi, bpair& lo) {
    __nv_bfloat162 h01 = __floats2bfloat162_rn(v.x, v.y);
    __nv_bfloat162 h23 = __floats2bfloat162_rn(v.z, v.w);
    float2 f01 = __bfloat1622float2(h01);
    float2 f23 = __bfloat1622float2(h23);
    hi.a = h01; hi.b = h23;
    lo.a = __floats2bfloat162_rn(v.x - f01.x, v.y - f01.y);
    lo.b = __floats2bfloat162_rn(v.z - f23.x, v.w - f23.y);
}

__device__ __forceinline__ uint32_t smem_u32(const void* p) {
    uint32_t a;
    asm("{ .reg .u64 t; cvta.to.shared.u64 t, %1; cvt.u32.u64 %0, t; }" : "=r"(a) : "l"(p));
    return a;
}
__device__ __forceinline__ uint32_t elect1() {
    uint32_t r;
    asm volatile("{ .reg .pred p; elect.sync _|p, 0xFFFFFFFF; selp.b32 %0, 1, 0, p; }" : "=r"(r));
    return r;
}
__device__ __forceinline__ void mbar_init(uint32_t a, uint32_t cnt) {
    asm volatile("mbarrier.init.shared.b64 [%0], %1;" :: "r"(a), "r"(cnt) : "memory");
}
__device__ __forceinline__ void mbar_inval(uint32_t a) {
    asm volatile("mbarrier.inval.shared.b64 [%0];" :: "r"(a) : "memory");
}
__device__ __forceinline__ void mbar_wait(uint32_t a, uint32_t parity) {
    asm volatile(
        "{\n\t.reg .pred P;\n\t"
        "W_%=:\n\t"
        "mbarrier.try_wait.parity.acquire.cta.shared::cta.b64 P, [%0], %1, 0x989680;\n\t"
        "@P bra D_%=;\n\t"
        "bra W_%=;\n\t"
        "D_%=:\n\t}"
        :: "r"(a), "r"(parity) : "memory");
}
__device__ __forceinline__ void mma_bf16(uint32_t d, uint64_t ad, uint64_t bd,
                                         uint32_t idesc, uint32_t en) {
    asm volatile(
        "{\n\t.reg .pred p;\n\tsetp.ne.u32 p, %5, 0;\n\t"
        "tcgen05.mma.cta_group::1.kind::f16 [%0], %1, %2, %3, {%4, %4, %4, %4}, p;\n\t}"
        :: "r"(d), "l"(ad), "l"(bd), "r"(idesc), "r"(0u), "r"(en) : "memory");
}
__device__ __forceinline__ void tc_commit(uint32_t mbar) {
    asm volatile(
        "tcgen05.commit.cta_group::1.mbarrier::arrive::one.shared::cluster.b64 [%0];"
        :: "r"(mbar) : "memory");
}
#define TC_ALLOC(sa, n)   asm volatile("tcgen05.alloc.cta_group::1.sync.aligned.shared::cta.b32 [%0], %1;" :: "r"(sa), "r"(n) : "memory")
#define TC_RELINQ()       asm volatile("tcgen05.relinquish_alloc_permit.cta_group::1.sync.aligned;")
#define TC_DEALLOC(t, n)  asm volatile("tcgen05.dealloc.cta_group::1.sync.aligned.b32 %0, %1;" :: "r"(t), "r"(n))
#define TC_WAIT_LD()      asm volatile("tcgen05.wait::ld.sync.aligned;" ::: "memory")
#define TC_WAIT_ST()      asm volatile("tcgen05.wait::st.sync.aligned;" ::: "memory")
#define TC_FENCE_BEFORE() asm volatile("tcgen05.fence::before_thread_sync;" ::: "memory")
#define TC_FENCE_AFTER()  asm volatile("tcgen05.fence::after_thread_sync;" ::: "memory")
#define FENCE_ASYNC()     asm volatile("fence.proxy.async.shared::cta;" ::: "memory")

#define LDTM_X32(r, a) \
    asm volatile("tcgen05.ld.sync.aligned.32x32b.x32.b32 " \
        "{%0,%1,%2,%3,%4,%5,%6,%7,%8,%9,%10,%11,%12,%13,%14,%15," \
        "%16,%17,%18,%19,%20,%21,%22,%23,%24,%25,%26,%27,%28,%29,%30,%31}, [%32];" \
        : "=r"((r)[0]),"=r"((r)[1]),"=r"((r)[2]),"=r"((r)[3]),"=r"((r)[4]),"=r"((r)[5]),"=r"((r)[6]),"=r"((r)[7]), \
          "=r"((r)[8]),"=r"((r)[9]),"=r"((r)[10]),"=r"((r)[11]),"=r"((r)[12]),"=r"((r)[13]),"=r"((r)[14]),"=r"((r)[15]), \
          "=r"((r)[16]),"=r"((r)[17]),"=r"((r)[18]),"=r"((r)[19]),"=r"((r)[20]),"=r"((r)[21]),"=r"((r)[22]),"=r"((r)[23]), \
          "=r"((r)[24]),"=r"((r)[25]),"=r"((r)[26]),"=r"((r)[27]),"=r"((r)[28]),"=r"((r)[29]),"=r"((r)[30]),"=r"((r)[31]) \
        : "r"(a))
#define LDTM_X16(r, a) \
    asm volatile("tcgen05.ld.sync.aligned.32x32b.x16.b32 " \
        "{%0,%1,%2,%3,%4,%5,%6,%7,%8,%9,%10,%11,%12,%13,%14,%15}, [%16];" \
        : "=r"((r)[0]),"=r"((r)[1]),"=r"((r)[2]),"=r"((r)[3]),"=r"((r)[4]),"=r"((r)[5]),"=r"((r)[6]),"=r"((r)[7]), \
          "=r"((r)[8]),"=r"((r)[9]),"=r"((r)[10]),"=r"((r)[11]),"=r"((r)[12]),"=r"((r)[13]),"=r"((r)[14]),"=r"((r)[15]) \
        : "r"(a))
#define STTM_X16(a, r) \
    asm volatile("tcgen05.st.sync.aligned.32x32b.x16.b32 [%0], " \
        "{%1,%2,%3,%4,%5,%6,%7,%8,%9,%10,%11,%12,%13,%14,%15,%16};" \
        :: "r"(a), \
           "r"((r)[0]),"r"((r)[1]),"r"((r)[2]),"r"((r)[3]),"r"((r)[4]),"r"((r)[5]),"r"((r)[6]),"r"((r)[7]), \
           "r"((r)[8]),"r"((r)[9]),"r"((r)[10]),"r"((r)[11]),"r"((r)[12]),"r"((r)[13]),"r"((r)[14]),"r"((r)[15]) \
        : "memory")

// ---------------- prep ----------------
__global__ void prep_kernel(const float* __restrict__ encW1, const float* __restrict__ encb1,
                            const float* __restrict__ encW2, const float* __restrict__ encb2,
                            const float* __restrict__ gmW1,  const float* __restrict__ gmb1,
                            const float* __restrict__ bih,   const float* __restrict__ bhh)
{
    int tid = threadIdx.x;
    if (tid < 288) {
        int k = tid / 96, j = tid % 96;
        float acc = encb2[j];
        #pragma unroll
        for (int i = 0; i < 16; i++) {
            float e = fmaxf(encW1[k*16 + i] + encb1[i], 0.f);
            acc += e * encW2[i*96 + j];
        }
        d_xcat[tid] = acc;
    }
    if (tid < 384) d_biasC[tid] = bih[tid] + bhh[tid];
    __syncthreads();
    if (tid < 288) {
        int k = tid / 96, j = tid % 96;
        float acc = gmb1[j];
        for (int t = 0; t < 96; t++) acc += d_xcat[k*96 + t] * gmW1[t*96 + j];
        d_xw1[tid] = acc;
    }
    if (tid < 81) {
        int m = tid, cnt = 0;
        int r = m / 9, c = m % 9, br = r / 3, bc = c / 3;
        for (int n = 0; n < 81; n++) {
            if (n == m) continue;
            int r2 = n / 9, c2 = n % 9;
            if (r2 == r || c2 == c || (r2/3 == br && c2/3 == bc)) d_nbr[m*20 + cnt++] = n;
        }
    }
}

// ---------------- weight split/transposes (once per run) ----------------
struct Ptr12 { const float* p[12]; };
__global__ void split_sq_kernel(Ptr12 srcs)
{
    int m = blockIdx.y;
    int idx = blockIdx.x * 256 + threadIdx.x;
    if (idx >= 9216) return;
    int k = idx / 96, n = idx % 96;
    float v = srcs.p[m][k*96 + n];
    __nv_bfloat16 hi = __float2bfloat16(v);
    d_Wsq_hi[m*9216 + n*96 + k] = hi;
    d_Wsq_lo[m*9216 + n*96 + k] = __float2bfloat16(v - __bfloat162float(hi));
}
__global__ void split_lstm_kernel(const float* __restrict__ Wih, const float* __restrict__ Whh)
{
    int idx = blockIdx.x * 256 + threadIdx.x;
    if (idx >= 36864) return;
    float v = Wih[idx];
    __nv_bfloat16 hi = __float2bfloat16(v);
    d_Wih_hi[idx] = hi; d_Wih_lo[idx] = __float2bfloat16(v - __bfloat162float(hi));
    v = Whh[idx];
    hi = __float2bfloat16(v);
    d_Whh_hi[idx] = hi; d_Whh_lo[idx] = __float2bfloat16(v - __bfloat162float(hi));
}

// ---------------- init ----------------
__global__ void init_kernel(const int* __restrict__ inputs, const float* __restrict__ c0)
{
    int idx = blockIdx.x * blockDim.x + threadIdx.x;  // MROWS*24
    if (idx >= MROWS * 24) return;
    int r = idx / 24, q = idx % 24;
    int bn = r / 9, dd = r % 9;
    int v = inputs[bn];
    int cat = (v == 0) ? 0 : ((v == dd + 1) ? 1 : 2);
    if (q == 0) d_cat[r] = (unsigned char)cat;
    *(float4*)(d_h + (size_t)r*96 + q*4) = *(const float4*)(d_xcat + cat*96 + q*4);
    *(float4*)(d_c + (size_t)r*96 + q*4) = *(const float4*)(c0 + (size_t)r*96 + q*4);
}

// ---------------- SMEM layout (bf16 SW64 blocked atoms) ----------------
#define SA_HI 1024
#define SA_LO 25600
#define SW_HI 50176
#define SW_LO 68608
#define SMEM_BYTES 87040

__device__ __forceinline__ uint32_t swA(int r, int k) {
    uint32_t byte = (uint32_t)((r >> 3) + (k >> 5) * 16) * 512u
                  + (uint32_t)(r & 7) * 64u + (uint32_t)(k & 31) * 2u;
    return byte ^ ((byte >> 3) & 0x30);
}
__device__ __forceinline__ uint32_t swW(int n, int k) {
    uint32_t byte = (uint32_t)((n >> 3) + (k >> 5) * 12) * 512u
                  + (uint32_t)(n & 7) * 64u + (uint32_t)(k & 31) * 2u;
    return byte ^ ((byte >> 3) & 0x30);
}

#define IDESC_BF16 ((1u<<4) | (1u<<7) | (1u<<10) | (12u<<17) | (8u<<24))
#define DBASE_SW64 ((4ull<<61) | (1ull<<46) | (32ull<<32) | (1ull<<16))

__device__ __forceinline__ void mma_layer(uint32_t dtm, uint64_t ah, uint64_t al,
                                          uint64_t wh, uint64_t wl, bool accum) {
    #pragma unroll
    for (int j = 0; j < 6; j++) {
        uint64_t aoff = (uint64_t)((j >> 1) * 512 + (j & 1) * 2);
        uint64_t woff = (uint64_t)((j >> 1) * 384 + (j & 1) * 2);
        mma_bf16(dtm, ah + aoff, wh + woff, IDESC_BF16, (!accum && j == 0) ? 0u : 1u);
        mma_bf16(dtm, al + aoff, wh + woff, IDESC_BF16, 1u);
        mma_bf16(dtm, ah + aoff, wl + woff, IDESC_BF16, 1u);
    }
}

template<int NSRC>
__device__ __forceinline__ int lw_off(int l, int src) {
    return (l == 0 ? src : (NSRC - 1 + l)) * 9216;
}

__device__ __forceinline__ void load_split_A(char* smem, const float* A, int row0, int tid) {
    #pragma unroll
    for (int i = 0; i < 12; i++) {
        int idx = i * 256 + tid;
        int rA = idx / 24, k = (idx % 24) * 4;
        float4 v = *(const float4*)(A + (size_t)(row0 + rA)*96 + k);
        bpair hi, lo;
        bsplit4(v, hi, lo);
        uint32_t sw = swA(rA, k);
        *(bpair*)(smem + SA_HI + sw) = hi;
        *(bpair*)(smem + SA_LO + sw) = lo;
    }
}
// A = S[bn] - t1[r]  (msg_cell computed on the fly)
__device__ __forceinline__ void load_split_A_mc(char* smem, const float* t1,
                                                const float* S, int row0, int tid) {
    #pragma unroll
    for (int i = 0; i < 12; i++) {
        int idx = i * 256 + tid;
        int rA = idx / 24, k = (idx % 24) * 4;
        int r = row0 + rA;
        float4 a = *(const float4*)(t1 + (size_t)r*96 + k);
        float4 s = *(const float4*)(S + (size_t)(r/9)*96 + k);
        float4 v = make_float4(s.x - a.x, s.y - a.y, s.z - a.z, s.w - a.w);
        bpair hi, lo;
        bsplit4(v, hi, lo);
        uint32_t sw = swA(rA, k);
        *(bpair*)(smem + SA_HI + sw) = hi;
        *(bpair*)(smem + SA_LO + sw) = lo;
    }
}
__device__ __forceinline__ void load_W(char* smem, const __nv_bfloat16* Wh,
                                       const __nv_bfloat16* Wl, int tid) {
    #pragma unroll
    for (int i = 0; i < 9; i++) {
        int idx = i * 256 + tid;
        int n = idx / 24, k = (idx % 24) * 4;
        uint32_t sw = swW(n, k);
        *(uint2*)(smem + SW_HI + sw) = *(const uint2*)(Wh + (size_t)n*96 + k);
        *(uint2*)(smem + SW_LO + sw) = *(const uint2*)(Wl + (size_t)n*96 + k);
    }
}

// ---- W prefetch: LDG into regs (overlaps mbar wait), STS after wait ----
#define LDG_W(Wh_, Wl_) do {                                                  \
    const __nv_bfloat16* _wh = (Wh_);                                         \
    const __nv_bfloat16* _wl = (Wl_);                                         \
    _Pragma("unroll")                                                         \
    for (int i = 0; i < 9; i++) {                                             \
        int idx = i * 256 + tid;                                              \
        int n = idx / 24, k = (idx % 24) * 4;                                 \
        wph[i] = *(const uint2*)(_wh + (size_t)n*96 + k);                     \
        wpl[i] = *(const uint2*)(_wl + (size_t)n*96 + k);                     \
    }                                                                         \
} while (0)
#define STS_W() do {                                                          \
    _Pragma("unroll")                                                         \
    for (int i = 0; i < 9; i++) {                                             \
        int idx = i * 256 + tid;                                              \
        int n = idx / 24, k = (idx % 24) * 4;                                 \
        uint32_t sw = swW(n, k);                                              \
        *(uint2*)(smem + SW_HI + sw) = wph[i];                                \
        *(uint2*)(smem + SW_LO + sw) = wpl[i];                                \
    }                                                                         \
} while (0)

// =====================================================================
// Fused MLP chain (bf16x3): NL layers, intermediates on-chip.
// BIAS0: 1 = layer0 bias is xw1[cat]. EPIF: 0 = plain store; 3 = head.
// FBSCR: fallback scratch selector. MCMODE: 1 = src0 A is S[bn]-A0[r].
// =====================================================================
template<int NL, int NSRC, int BIAS0, int EPIF, int FBSCR, int MCMODE>
__global__ void __launch_bounds__(256, 2) tchain_kernel(
    const float* __restrict__ A0, const float* __restrict__ A1,
    const __nv_bfloat16* __restrict__ Whi, const __nv_bfloat16* __restrict__ Wlo,
    const float* __restrict__ biases, const float* __restrict__ w3,
    const float* __restrict__ b3, float* __restrict__ C,
    const float* __restrict__ Sp)
{
#if defined(__CUDA_ARCH_FEAT_SM103_ALL)
    extern __shared__ char smem[];
    const uint32_t sb = smem_u32(smem);
    const int tid = threadIdx.x;
    const int warp = tid >> 5;
    const int lane = tid & 31;
    const int row0 = blockIdx.x * 128;

    if (warp == 0) { TC_ALLOC(sb, 256); TC_RELINQ(); }
    if (tid == 0)  mbar_init(sb + 8, 1);
    __syncthreads();
    uint32_t tmem;
    asm volatile("ld.shared.b32 %0, [%1];" : "=r"(tmem) : "r"(sb));

    const uint64_t ahd = DBASE_SW64 | (((uint64_t)(sb + SA_HI) >> 4) & 0x3FFF);
    const uint64_t ald = DBASE_SW64 | (((uint64_t)(sb + SA_LO) >> 4) & 0x3FFF);
    const uint64_t whd = DBASE_SW64 | (((uint64_t)(sb + SW_HI) >> 4) & 0x3FFF);
    const uint64_t wld = DBASE_SW64 | (((uint64_t)(sb + SW_LO) >> 4) & 0x3FFF);
    int wave = 0;
    uint2 wph[9], wpl[9];

    const int sub  = warp & 3;
    const int half = warp >> 2;
    const int rr   = sub * 32 + lane;
    const int r    = row0 + rr;
    const uint32_t woff = (uint32_t)sub << 21;
    const int coff = half * 48;

    LDG_W(Whi + lw_off<NSRC>(0, 0), Wlo + lw_off<NSRC>(0, 0));

    #pragma unroll
    for (int src = 0; src < NSRC; src++) {
        if (MCMODE == 1 && src == 0)
            load_split_A_mc(smem, A0, Sp, row0, tid);
        else
            load_split_A(smem, src ? A1 : A0, row0, tid);
        STS_W();
        FENCE_ASYNC();
        __syncthreads();
        if (warp == 0 && elect1()) {
            mma_layer(tmem, ahd, ald, whd, wld, src != 0);
            tc_commit(sb + 8);
        }
        if (src + 1 < NSRC)
            LDG_W(Whi + lw_off<NSRC>(0, src + 1), Wlo + lw_off<NSRC>(0, src + 1));
        else if (NL > 1)
            LDG_W(Whi + lw_off<NSRC>(1, 0), Wlo + lw_off<NSRC>(1, 0));
        mbar_wait(sb + 8, wave & 1); wave++;
    }

    #pragma unroll
    for (int l = 1; l < NL; l++) {
        STS_W();
        TC_FENCE_AFTER();
        uint32_t dsel = (uint32_t)((l - 1) & 1) * 128u;
        uint32_t dreg[48];
        LDTM_X32(dreg,      tmem + dsel + woff + coff);
        LDTM_X16(dreg + 32, tmem + dsel + woff + coff + 32);
        TC_WAIT_LD();
        float vals[48];
        {
            const int lprev = l - 1;
            const float* bv = (BIAS0 == 1 && lprev == 0)
                            ? (d_xw1 + (int)d_cat[r]*96 + coff)
                            : (biases + (lprev - BIAS0)*96 + coff);
            #pragma unroll
            for (int u = 0; u < 48; u++)
                vals[u] = fmaxf(__uint_as_float(dreg[u]) + bv[u], 0.f);
        }
        #pragma unroll
        for (int u4 = 0; u4 < 12; u4++) {
            int k = coff + u4*4;
            float4 v = make_float4(vals[u4*4], vals[u4*4+1], vals[u4*4+2], vals[u4*4+3]);
            bpair hi, lo;
            bsplit4(v, hi, lo);
            uint32_t sw = swA(rr, k);
            *(bpair*)(smem + SA_HI + sw) = hi;
            *(bpair*)(smem + SA_LO + sw) = lo;
        }
        FENCE_ASYNC();
        __syncthreads();
        if (warp == 0 && elect1()) {
            mma_layer(tmem + (uint32_t)(l & 1) * 128u, ahd, ald, whd, wld, false);
            tc_commit(sb + 8);
        }
        if (l + 1 < NL)
            LDG_W(Whi + lw_off<NSRC>(l + 1, 0), Wlo + lw_off<NSRC>(l + 1, 0));
        mbar_wait(sb + 8, wave & 1); wave++;
    }

    TC_FENCE_AFTER();
    {
        uint32_t dsel = (uint32_t)((NL - 1) & 1) * 128u;
        uint32_t dreg[48];
        LDTM_X32(dreg,      tmem + dsel + woff + coff);
        LDTM_X16(dreg + 32, tmem + dsel + woff + coff + 32);
        TC_WAIT_LD();
        const int lf = NL - 1;
        const float* bv = (BIAS0 == 1 && lf == 0)
                        ? (d_xw1 + (int)d_cat[r]*96 + coff)
                        : (biases + (lf - BIAS0)*96 + coff);
        if (EPIF == 3) {
            float part = 0.f;
            #pragma unroll
            for (int u = 0; u < 48; u++) {
                float v = fmaxf(__uint_as_float(dreg[u]) + bv[u], 0.f);
                part += v * w3[coff + u];
            }
            float* red = (float*)(smem + SA_HI);
            __syncthreads();
            red[tid] = part;
            __syncthreads();
            if (warp < 4)
                C[r] = red[tid] + red[tid + 128] + b3[0];
        } else {
            float vals[48];
            #pragma unroll
            for (int u = 0; u < 48; u++)
                vals[u] = __uint_as_float(dreg[u]) + bv[u];
            #pragma unroll
            for (int u = 0; u < 12; u++)
                *(float4*)(C + (size_t)r*96 + coff + u*4) = *(float4*)(vals + u*4);
        }
    }

    __syncthreads();
    if (tid == 0) mbar_inval(sb + 8);
    if (warp == 0) { TC_DEALLOC(tmem, 256); }
#else
    // ================= fallback (plain sm_103): FFMA layer loop =====
    float* scratch = FBSCR ? d_t5 : d_t4;
    __shared__ float As[16][132];
    __shared__ float Bs[16][97];
    const int tid = threadIdx.x;
    const int tx  = tid & 15;
    const int ty  = tid >> 4;
    const int row0 = blockIdx.x * 128;
    const int qk = tid & 3;
    const int rrf = tid >> 2;

    #pragma unroll 1
    for (int l = 0; l < NL; l++) {
        float acc[8][6];
        #pragma unroll
        for (int i = 0; i < 8; i++)
            #pragma unroll
            for (int u = 0; u < 6; u++) acc[i][u] = 0.f;
        const int ns = (l == 0) ? NSRC : 1;
        #pragma unroll 1
        for (int s = 0; s < ns; s++) {
            const float* A = (l == 0) ? (s ? A1 : A0) : scratch;
            const bool mc = (MCMODE == 1 && l == 0 && s == 0);
            const __nv_bfloat16* Wh = Whi + lw_off<NSRC>(l, s);
            const __nv_bfloat16* Wl = Wlo + lw_off<NSRC>(l, s);
            #pragma unroll 1
            for (int ct = 0; ct < 6; ct++) {
                const int k0 = ct * 16;
                float4 v0 = *(const float4*)(A + (size_t)(row0 + rrf     )*96 + k0 + qk*4);
                float4 v1 = *(const float4*)(A + (size_t)(row0 + rrf + 64)*96 + k0 + qk*4);
                if (mc) {
                    float4 s0 = *(const float4*)(Sp + (size_t)((row0 + rrf     )/9)*96 + k0 + qk*4);
                    float4 s1 = *(const float4*)(Sp + (size_t)((row0 + rrf + 64)/9)*96 + k0 + qk*4);
                    v0 = make_float4(s0.x - v0.x, s0.y - v0.y, s0.z - v0.z, s0.w - v0.w);
                    v1 = make_float4(s1.x - v1.x, s1.y - v1.y, s1.z - v1.z, s1.w - v1.w);
                }
                float bl[6];
                #pragma unroll
                for (int u = 0; u < 6; u++) {
                    int idx = tid + 256*u;
                    int n = idx >> 4, kk = idx & 15;
                    bl[u] = __bfloat162float(Wh[(size_t)n*96 + k0 + kk])
                          + __bfloat162float(Wl[(size_t)n*96 + k0 + kk]);
                }
                __syncthreads();
                As[qk*4+0][rrf]    = v0.x; As[qk*4+1][rrf]    = v0.y;
                As[qk*4+2][rrf]    = v0.z; As[qk*4+3][rrf]    = v0.w;
                As[qk*4+0][rrf+64] = v1.x; As[qk*4+1][rrf+64] = v1.y;
                As[qk*4+2][rrf+64] = v1.z; As[qk*4+3][rrf+64] = v1.w;
                #pragma unroll
                for (int u = 0; u < 6; u++) {
                    int idx = tid + 256*u;
                    Bs[idx & 15][idx >> 4] = bl[u];
                }
                __syncthreads();
                #pragma unroll
                for (int k = 0; k < 16; k++) {
                    float a[8];
                    #pragma unroll
                    for (int i = 0; i < 8; i++) a[i] = As[k][ty*8 + i];
                    float b[6];
                    #pragma unroll
                    for (int u = 0; u < 6; u++) b[u] = Bs[k][tx + 16*u];
                    #pragma unroll
                    for (int i = 0; i < 8; i++)
                        #pragma unroll
                        for (int u = 0; u < 6; u++) acc[i][u] = fmaf(a[i], b[u], acc[i][u]);
                }
            }
        }
        const bool relu = (l < NL - 1) || (EPIF == 3);
        const bool last = (l == NL - 1);
        float* dst = (last && EPIF == 0) ? C : scratch;
        float bv[6];
        if (!(BIAS0 == 1 && l == 0)) {
            #pragma unroll
            for (int u = 0; u < 6; u++) bv[u] = biases[(l - BIAS0)*96 + tx + 16*u];
        }
        #pragma unroll
        for (int i = 0; i < 8; i++) {
            int rW = row0 + ty*8 + i;
            const float* xb = (BIAS0 == 1 && l == 0) ? (d_xw1 + (int)d_cat[rW]*96) : nullptr;
            #pragma unroll
            for (int u = 0; u < 6; u++) {
                float v = acc[i][u] + ((BIAS0 == 1 && l == 0) ? xb[tx + 16*u] : bv[u]);
                if (relu) v = fmaxf(v, 0.f);
                dst[(size_t)rW*96 + tx + 16*u] = v;
            }
        }
        __syncthreads();
    }
    if (EPIF == 3) {
        const int warp = tid >> 5, lane = tid & 31;
        for (int i = 0; i < 16; i++) {
            int r = row0 + warp*16 + i;
            const float* x = scratch + (size_t)r*96;
            float s = x[lane]*w3[lane] + x[lane+32]*w3[lane+32] + x[lane+64]*w3[lane+64];
            #pragma unroll
            for (int o = 16; o; o >>= 1) s += __shfl_xor_sync(0xffffffffu, s, o);
            if (lane == 0) C[r] = s + b3[0];
        }
    }
#endif
}

// =====================================================================
// LSTM GEMM: TMEM 256 (2 banks of 96), gates in phases (i,g)->(f)->(o),
// u / tanh(c') staged through TMEM bank X1 via STTM. occ 2, W prefetch.
// =====================================================================
__global__ void __launch_bounds__(256, 2) tlstm_kernel(
    const float* __restrict__ A0, const float* __restrict__ A1,
    const __nv_bfloat16* __restrict__ W0hi, const __nv_bfloat16* __restrict__ W0lo,
    const __nv_bfloat16* __restrict__ W1hi, const __nv_bfloat16* __restrict__ W1lo,
    const float* __restrict__ bias, float* __restrict__ C, float* __restrict__ cst)
{
#if defined(__CUDA_ARCH_FEAT_SM103_ALL)
    extern __shared__ char smem[];
    const uint32_t sb = smem_u32(smem);
    const int tid = threadIdx.x;
    const int warp = tid >> 5;
    const int lane = tid & 31;
    const int row0 = blockIdx.x * 128;

    if (warp == 0) { TC_ALLOC(sb, 256); TC_RELINQ(); }
    if (tid == 0)  mbar_init(sb + 8, 1);
    __syncthreads();
    uint32_t tmem;
    asm volatile("ld.shared.b32 %0, [%1];" : "=r"(tmem) : "r"(sb));

    const uint64_t ahd = DBASE_SW64 | (((uint64_t)(sb + SA_HI) >> 4) & 0x3FFF);
    const uint64_t ald = DBASE_SW64 | (((uint64_t)(sb + SA_LO) >> 4) & 0x3FFF);
    const uint64_t whd = DBASE_SW64 | (((uint64_t)(sb + SW_HI) >> 4) & 0x3FFF);
    const uint64_t wld = DBASE_SW64 | (((uint64_t)(sb + SW_LO) >> 4) & 0x3FFF);
    int wave = 0;
    uint2 wph[9], wpl[9];

    const int sub  = warp & 3;
    const int half = warp >> 2;
    const int r    = row0 + sub * 32 + lane;
    const uint32_t woff = (uint32_t)sub << 21;
    const int coff = half * 48;

// stage: STS prefetched W, (opt) load A, sync, MMA+commit, prefetch next W, wait
#define LSTM_STAGE(bank_, acc_, APTR_, NWh_, NWl_) do {                       \
    STS_W();                                                                  \
    if ((const float*)(APTR_) != nullptr)                                     \
        load_split_A(smem, (const float*)(APTR_), row0, tid);                 \
    FENCE_ASYNC();                                                            \
    __syncthreads();                                                          \
    if (warp == 0 && elect1()) {                                              \
        mma_layer(tmem + (bank_), ahd, ald, whd, wld, (acc_));                \
        tc_commit(sb + 8);                                                    \
    }                                                                         \
    if ((const __nv_bfloat16*)(NWh_) != nullptr)                              \
        LDG_W((const __nv_bfloat16*)(NWh_), (const __nv_bfloat16*)(NWl_));    \
    mbar_wait(sb + 8, wave & 1); wave++;                                      \
} while (0)

    LDG_W(W0hi, W0lo);                                    // Wih_i
    // ---- phase 1: gates i (bank0), g (bank96) ----
    LSTM_STAGE(0,  false, A0,      W0hi + 2*9216, W0lo + 2*9216);  // t3 @ Wih_i ; next Wih_g
    LSTM_STAGE(96, false, nullptr, W1hi,          W1lo);           // t3 @ Wih_g ; next Whh_i
    LSTM_STAGE(0,  true,  A1,      W1hi + 2*9216, W1lo + 2*9216);  // h  @ Whh_i ; next Whh_g
    LSTM_STAGE(96, true,  nullptr, W1hi + 1*9216, W1lo + 1*9216);  // h  @ Whh_g ; next Whh_f

    // E1: u = sig(i+bi) * tanh(g+bg)  -> STTM into bank0
    TC_FENCE_AFTER();
    #pragma unroll
    for (int ch = 0; ch < 3; ch++) {
        int col = coff + ch * 16;
        uint32_t ireg[16], greg[16], ureg[16];
        LDTM_X16(ireg, tmem + woff + col);
        LDTM_X16(greg, tmem + 96 + woff + col);
        TC_WAIT_LD();
        #pragma unroll
        for (int u = 0; u < 16; u++) {
            float iv = sigf(__uint_as_float(ireg[u]) + bias[col + u]);
            float gv = tanhff(__uint_as_float(greg[u]) + bias[192 + col + u]);
            ureg[u] = __float_as_uint(iv * gv);
        }
        STTM_X16(tmem + woff + col, ureg);
    }
    TC_WAIT_ST();
    TC_FENCE_BEFORE();
    __syncthreads();

    // ---- phase 2a: gate f (bank96) ----
    LSTM_STAGE(96, false, nullptr, W0hi + 1*9216, W0lo + 1*9216);  // h  @ Whh_f ; next Wih_f
    LSTM_STAGE(96, true,  A0,      W0hi + 3*9216, W0lo + 3*9216);  // t3 @ Wih_f ; next Wih_o

    // E2: c' = sig(f+bf)*c_old + u; store c'; STTM tanh(c') -> bank0
    TC_FENCE_AFTER();
    #pragma unroll
    for (int ch = 0; ch < 3; ch++) {
        int col = coff + ch * 16;
        uint32_t freg[16], ureg[16], treg[16];
        LDTM_X16(freg, tmem + 96 + woff + col);
        LDTM_X16(ureg, tmem + woff + col);
        TC_WAIT_LD();
        float ncv[16];
        #pragma unroll
        for (int u4 = 0; u4 < 4; u4++) {
            float4 cold = *(const float4*)(cst + (size_t)r*96 + col + u4*4);
            float co[4] = {cold.x, cold.y, cold.z, cold.w};
            #pragma unroll
            for (int e = 0; e < 4; e++) {
                int u = u4*4 + e;
                float fv = sigf(__uint_as_float(freg[u]) + bias[96 + col + u]);
                float nc = fv * co[e] + __uint_as_float(ureg[u]);
                ncv[u] = nc;
                treg[u] = __float_as_uint(tanhff(nc));
            }
        }
        #pragma unroll
        for (int u4 = 0; u4 < 4; u4++)
            *(float4*)(cst + (size_t)r*96 + col + u4*4) = *(float4*)(ncv + u4*4);
        STTM_X16(tmem + woff + col, treg);
    }
    TC_WAIT_ST();
    TC_FENCE_BEFORE();
    __syncthreads();

    // ---- phase 2b: gate o (bank96) ----
    LSTM_STAGE(96, false, nullptr, W1hi + 3*9216, W1lo + 3*9216);  // t3 @ Wih_o ; next Whh_o
    LSTM_STAGE(96, true,  A1,      nullptr,       nullptr);        // h  @ Whh_o

    // E3: h' = sig(o+bo) * tanh(c')
    TC_FENCE_AFTER();
    #pragma unroll
    for (int ch = 0; ch < 3; ch++) {
        int col = coff + ch * 16;
        uint32_t oreg[16], treg[16];
        LDTM_X16(oreg, tmem + 96 + woff + col);
        LDTM_X16(treg, tmem + woff + col);
        TC_WAIT_LD();
        float hv[16];
        #pragma unroll
        for (int u = 0; u < 16; u++) {
            float ov = sigf(__uint_as_float(oreg[u]) + bias[288 + col + u]);
            hv[u] = ov * __uint_as_float(treg[u]);
        }
        #pragma unroll
        for (int u4 = 0; u4 < 4; u4++)
            *(float4*)(C + (size_t)r*96 + col + u4*4) = *(float4*)(hv + u4*4);
    }

    __syncthreads();
    if (tid == 0) mbar_inval(sb + 8);
    if (warp == 0) { TC_DEALLOC(tmem, 256); }
#undef LSTM_STAGE
#else
    // fallback: gates to d_gates then fused elementwise
    __shared__ float As[16][132];
    __shared__ float Bs[16][97];
    const int tid = threadIdx.x;
    const int tx  = tid & 15;
    const int ty  = tid >> 4;
    const int row0 = blockIdx.x * 128;
    const int qk = tid & 3;
    const int rrf = tid >> 2;

    #pragma unroll 1
    for (int g = 0; g < 4; g++) {
        float acc[8][6];
        #pragma unroll
        for (int i = 0; i < 8; i++)
            #pragma unroll
            for (int u = 0; u < 6; u++) acc[i][u] = 0.f;
        #pragma unroll
        for (int s = 0; s < 2; s++) {
            const float* A = s ? A1 : A0;
            const __nv_bfloat16* Wh = (s ? W1hi : W0hi) + (size_t)g*9216;
            const __nv_bfloat16* Wl = (s ? W1lo : W0lo) + (size_t)g*9216;
            #pragma unroll 1
            for (int ct = 0; ct < 6; ct++) {
                const int k0 = ct * 16;
                float4 v0 = *(const float4*)(A + (size_t)(row0 + rrf     )*96 + k0 + qk*4);
                float4 v1 = *(const float4*)(A + (size_t)(row0 + rrf + 64)*96 + k0 + qk*4);
                float bl[6];
                #pragma unroll
                for (int u = 0; u < 6; u++) {
                    int idx = tid + 256*u;
                    int n = idx >> 4, kk = idx & 15;
                    bl[u] = __bfloat162float(Wh[(size_t)n*96 + k0 + kk])
                          + __bfloat162float(Wl[(size_t)n*96 + k0 + kk]);
                }
                __syncthreads();
                As[qk*4+0][rrf]    = v0.x; As[qk*4+1][rrf]    = v0.y;
                As[qk*4+2][rrf]    = v0.z; As[qk*4+3][rrf]    = v0.w;
                As[qk*4+0][rrf+64] = v1.x; As[qk*4+1][rrf+64] = v1.y;
                As[qk*4+2][rrf+64] = v1.z; As[qk*4+3][rrf+64] = v1.w;
                #pragma unroll
                for (int u = 0; u < 6; u++) {
                    int idx = tid + 256*u;
                    Bs[idx & 15][idx >> 4] = bl[u];
                }
                __syncthreads();
                #pragma unroll
                for (int k = 0; k < 16; k++) {
                    float a[8];
                    #pragma unroll
                    for (int i = 0; i < 8; i++) a[i] = As[k][ty*8 + i];
                    float b[6];
                    #pragma unroll
                    for (int u = 0; u < 6; u++) b[u] = Bs[k][tx + 16*u];
                    #pragma unroll
                    for (int i = 0; i < 8; i++)
                        #pragma unroll
                        for (int u = 0; u < 6; u++) acc[i][u] = fmaf(a[i], b[u], acc[i][u]);
                }
            }
        }
        #pragma unroll
        for (int i = 0; i < 8; i++) {
            int rW = row0 + ty*8 + i;
            #pragma unroll
            for (int u = 0; u < 6; u++)
                d_gates[(size_t)rW*384 + g*96 + tx + 16*u] = acc[i][u] + bias[g*96 + tx + 16*u];
        }
    }
    __syncthreads();
    #pragma unroll
    for (int u = 0; u < 12; u++) {
        int e = tid + u*256;
        int r = row0 + e/24, q = (e%24)*4;
        const float* gp = d_gates + (size_t)r*384 + q;
        float4 gi = *(const float4*)(gp);
        float4 gf = *(const float4*)(gp + 96);
        float4 gg = *(const float4*)(gp + 192);
        float4 go = *(const float4*)(gp + 288);
        float4 co = *(const float4*)(cst + (size_t)r*96 + q);
        float4 nc, nh;
        nc.x = sigf(gf.x)*co.x + sigf(gi.x)*tanhff(gg.x);  nh.x = sigf(go.x)*tanhff(nc.x);
        nc.y = sigf(gf.y)*co.y + sigf(gi.y)*tanhff(gg.y);  nh.y = sigf(go.y)*tanhff(nc.y);
        nc.z = sigf(gf.z)*co.z + sigf(gi.z)*tanhff(gg.z);  nh.z = sigf(go.z)*tanhff(nc.z);
        nc.w = sigf(gf.w)*co.w + sigf(gi.w)*tanhff(gg.w);  nh.w = sigf(go.w)*tanhff(nc.w);
        *(float4*)(cst + (size_t)r*96 + q) = nc;
        *(float4*)(C   + (size_t)r*96 + q) = nh;
    }
#endif
}

// ---------------- msgS: S[bn] = sum_d t1[bn*9+d] ----------------
__global__ void msgS_kernel(const float* __restrict__ in, float* __restrict__ S)
{
    int idx = blockIdx.x * blockDim.x + threadIdx.x;
    if (idx >= BN_TOT * 24) return;
    int bn = idx / 24, q = idx % 24;
    const float* base = in + (size_t)bn*9*96 + q*4;
    float sx = 0, sy = 0, sz = 0, sw = 0;
    #pragma unroll
    for (int d = 0; d < 9; d++) {
        float4 x = *(const float4*)(base + d*96);
        sx += x.x; sy += x.y; sz += x.z; sw += x.w;
    }
    float4 o; o.x = sx; o.y = sy; o.z = sz; o.w = sw;
    *(float4*)(S + (size_t)bn*96 + q*4) = o;
}

// ---------------- msg_digit ----------------
__global__ void msgdigit_kernel(const float* __restrict__ in, float* __restrict__ out)
{
    __shared__ float4 sIn[81*24];
    __shared__ int snbr[81*20];
    int b = blockIdx.x, cz = blockIdx.y;
    const float* gbase = in + (size_t)b*81*864 + cz*96;
    for (int idx = threadIdx.x; idx < 81*24; idx += 256) {
        int n = idx / 24, q = idx % 24;
        sIn[n*24 + q] = *(const float4*)(gbase + (size_t)n*864 + q*4);
    }
    for (int idx = threadIdx.x; idx < 81*20; idx += 256) snbr[idx] = d_nbr[idx];
    __syncthreads();
    float* obase = out + (size_t)b*81*864 + cz*96;
    for (int idx = threadIdx.x; idx < 81*24; idx += 256) {
        int m = idx / 24, q = idx % 24;
        const int* nb = snbr + m*20;
        float4 s = {0.f, 0.f, 0.f, 0.f};
        #pragma unroll
        for (int e = 0; e < 20; e++) {
            float4 v = sIn[nb[e]*24 + q];
            s.x += v.x; s.y += v.y; s.z += v.z; s.w += v.w;
        }
        *(float4*)(obase + (size_t)m*864 + q*4) = s;
    }
}

// ---------------- static stream/event context ----------------
struct StreamCtx {
    cudaStream_t s1, s2;
    cudaEvent_t fork[5], j1[5], j2[5];
    bool ok;
    StreamCtx() : ok(false) {
        if (cudaStreamCreateWithFlags(&s1, cudaStreamNonBlocking) != cudaSuccess) return;
        if (cudaStreamCreateWithFlags(&s2, cudaStreamNonBlocking) != cudaSuccess) return;
        for (int i = 0; i < 5; i++) {
            if (cudaEventCreateWithFlags(&fork[i], cudaEventDisableTiming) != cudaSuccess) return;
            if (cudaEventCreateWithFlags(&j1[i],   cudaEventDisableTiming) != cudaSuccess) return;
            if (cudaEventCreateWithFlags(&j2[i],   cudaEventDisableTiming) != cudaSuccess) return;
        }
        ok = true;
    }
};
static StreamCtx g_ctx;

// ---------------- launch ----------------
extern "C" void kernel_launch(void* const* d_in, const int* in_sizes, int n_in,
                              void* d_out, int out_size)
{
    const int*   inputs = (const int*)  d_in[0];
    const float* c0     = (const float*)d_in[1];
    const float* encW1  = (const float*)d_in[4];
    const float* encb1  = (const float*)d_in[5];
    const float* encW2  = (const float*)d_in[6];
    const float* encb2  = (const float*)d_in[7];
    const float* crW    = (const float*)d_in[8];
    const float* crb    = (const float*)d_in[9];
    const float* drW    = (const float*)d_in[10];
    const float* drb    = (const float*)d_in[11];
    const float* gmW1   = (const float*)d_in[12];
    const float* gmb1   = (const float*)d_in[13];
    const float* gmW2   = (const float*)d_in[14];
    const float* gmb2   = (const float*)d_in[15];
    const float* Wih    = (const float*)d_in[16];
    const float* Whh    = (const float*)d_in[17];
    const float* bih    = (const float*)d_in[18];
    const float* bhh    = (const float*)d_in[19];
    const float* rW12   = (const float*)d_in[20];
    const float* rb12   = (const float*)d_in[21];
    const float* rW3    = (const float*)d_in[22];
    const float* rb3    = (const float*)d_in[23];
    float* out = (float*)d_out;

    float *h, *c, *t1, *t2, *t3, *md, *S, *biasC;
    __nv_bfloat16 *sqhi, *sqlo, *ihhi, *ihlo, *hhhi, *hhlo;
    cudaGetSymbolAddress((void**)&h,     d_h);
    cudaGetSymbolAddress((void**)&c,     d_c);
    cudaGetSymbolAddress((void**)&t1,    d_t1);
    cudaGetSymbolAddress((void**)&t2,    d_t2);
    cudaGetSymbolAddress((void**)&t3,    d_t3);
    cudaGetSymbolAddress((void**)&md,    d_md);
    cudaGetSymbolAddress((void**)&S,     d_S);
    cudaGetSymbolAddress((void**)&biasC, d_biasC);
    cudaGetSymbolAddress((void**)&sqhi,  d_Wsq_hi);
    cudaGetSymbolAddress((void**)&sqlo,  d_Wsq_lo);
    cudaGetSymbolAddress((void**)&ihhi,  d_Wih_hi);
    cudaGetSymbolAddress((void**)&ihlo,  d_Wih_lo);
    cudaGetSymbolAddress((void**)&hhhi,  d_Whh_hi);
    cudaGetSymbolAddress((void**)&hhlo,  d_Whh_lo);

    cudaFuncAttributes fa;
    cudaFuncGetAttributes(&fa, tchain_kernel<3,1,0,0,0,0>);
    const bool tc = (fa.sharedSizeBytes < 4096);
    const size_t SH = tc ? (size_t)SMEM_BYTES : 0;
    if (tc) {
        cudaFuncSetAttribute(tchain_kernel<3,1,0,0,0,0>, cudaFuncAttributeMaxDynamicSharedMemorySize, SMEM_BYTES);
        cudaFuncSetAttribute(tchain_kernel<3,1,0,0,1,0>, cudaFuncAttributeMaxDynamicSharedMemorySize, SMEM_BYTES);
        cudaFuncSetAttribute(tchain_kernel<3,2,1,0,0,1>, cudaFuncAttributeMaxDynamicSharedMemorySize, SMEM_BYTES);
        cudaFuncSetAttribute(tchain_kernel<2,1,0,3,0,0>, cudaFuncAttributeMaxDynamicSharedMemorySize, SMEM_BYTES);
        cudaFuncSetAttribute(tlstm_kernel, cudaFuncAttributeMaxDynamicSharedMemorySize, SMEM_BYTES);
    }

    const bool par = g_ctx.ok;
    cudaStream_t s0 = 0;
    cudaStream_t s1 = par ? g_ctx.s1 : s0;
    cudaStream_t s2 = par ? g_ctx.s2 : s0;

    prep_kernel<<<1, 384, 0, s0>>>(encW1, encb1, encW2, encb2, gmW1, gmb1, bih, bhh);
    Ptr12 ps;
    ps.p[0] = crW;          ps.p[1] = crW + 9216;   ps.p[2] = crW + 18432;
    ps.p[3] = drW;          ps.p[4] = drW + 9216;   ps.p[5] = drW + 18432;
    ps.p[6] = gmW1 + 9216;  ps.p[7] = gmW1 + 18432;
    ps.p[8] = gmW2;         ps.p[9] = gmW2 + 9216;
    ps.p[10] = rW12;        ps.p[11] = rW12 + 9216;
    split_sq_kernel<<<dim3(36, 12), 256, 0, s0>>>(ps);
    split_lstm_kernel<<<144, 256, 0, s0>>>(Wih, Whh);
    init_kernel<<<8748, 256, 0, s0>>>(inputs, c0);

    #define HI(i) (sqhi + (i)*9216)
    #define LO(i) (sqlo + (i)*9216)

    // --- pre-loop: t1/S, md from initial h (cr ∥ dr) ---
    if (par) {
        cudaEventRecord(g_ctx.fork[4], s0);
        cudaStreamWaitEvent(s1, g_ctx.fork[4], 0);
        cudaStreamWaitEvent(s2, g_ctx.fork[4], 0);
    }
    tchain_kernel<3,1,0,0,0,0><<<729,256,SH,s1>>>(h, nullptr, HI(0), LO(0), crb, nullptr, nullptr, t1, nullptr);
    msgS_kernel<<<972, 256, 0, s1>>>(t1, S);
    tchain_kernel<3,1,0,0,1,0><<<729,256,SH,s2>>>(h, nullptr, HI(3), LO(3), drb, nullptr, nullptr, t2, nullptr);
    msgdigit_kernel<<<dim3(128, 9), 256, 0, s2>>>(t2, md);
    if (par) {
        cudaEventRecord(g_ctx.j1[4], s1);
        cudaEventRecord(g_ctx.j2[4], s2);
        cudaStreamWaitEvent(s0, g_ctx.j1[4], 0);
        cudaStreamWaitEvent(s0, g_ctx.j2[4], 0);
    }

    for (int it = 0; it < 4; it++) {
        // serial spine: g-MLP (mc computed on the fly from t1/S) then LSTM
        tchain_kernel<3,2,1,0,0,1><<<729,256,SH,s0>>>(t1, md, HI(6), LO(6), gmb2, nullptr, nullptr, t3, S);
        tlstm_kernel<<<729,256,SH,s0>>>(t3, h, ihhi, ihlo, hhhi, hhlo, biasC, h, c);
        // parallel consumers of new h: head ∥ (cr→msgS) ∥ (dr→msgdigit)
        if (it < 3) {
            if (par) {
                cudaEventRecord(g_ctx.fork[it], s0);
                cudaStreamWaitEvent(s1, g_ctx.fork[it], 0);
                cudaStreamWaitEvent(s2, g_ctx.fork[it], 0);
            }
            tchain_kernel<3,1,0,0,0,0><<<729,256,SH,s1>>>(h, nullptr, HI(0), LO(0), crb, nullptr, nullptr, t1, nullptr);
            msgS_kernel<<<972, 256, 0, s1>>>(t1, S);
            tchain_kernel<3,1,0,0,1,0><<<729,256,SH,s2>>>(h, nullptr, HI(3), LO(3), drb, nullptr, nullptr, t2, nullptr);
            msgdigit_kernel<<<dim3(128, 9), 256, 0, s2>>>(t2, md);
            tchain_kernel<2,1,0,3,0,0><<<729,256,SH,s0>>>(h, nullptr, HI(10), LO(10), rb12, rW3, rb3, out + (size_t)it * MROWS, nullptr);
            if (par) {
                cudaEventRecord(g_ctx.j1[it], s1);
                cudaEventRecord(g_ctx.j2[it], s2);
                cudaStreamWaitEvent(s0, g_ctx.j1[it], 0);
                cudaStreamWaitEvent(s0, g_ctx.j2[it], 0);
            }
        } else {
            tchain_kernel<2,1,0,3,0,0><<<729,256,SH,s0>>>(h, nullptr, HI(10), LO(10), rb12, rW3, rb3, out + (size_t)it * MROWS, nullptr);
        }
    }
    #undef HI
    #undef LO
}